// round 11
// baseline (speedup 1.0000x reference)
#include <cuda_runtime.h>
#include <cuda_bf16.h>
#include <math.h>
#include <stdint.h>

// Problem constants
#define B_      64
#define NFEAT   196
#define ENC_Hc  2048
#define DEC_Hc  1024
#define ATTN_c  512
#define EMB_c   512
#define VOCAB_c 32000
#define TSTEPS  31
#define XDIM    (ENC_Hc + DEC_Hc)   // 3072
#define GDIM    (4 * DEC_Hc)        // 4096
#define SPLITK_GATES 8

// ---------------- scratch (device globals; no allocation allowed) -----------
__device__ float g_Uf[(size_t)B_ * NFEAT * ATTN_c];
__device__ float g_featmean[B_ * ENC_Hc];
__device__ float g_h[B_ * DEC_Hc];
__device__ float g_c[B_ * DEC_Hc];
__device__ float g_scores[B_ * NFEAT];
__device__ float g_GatesPart[SPLITK_GATES * B_ * GDIM];
__device__ float g_Gemb[(size_t)TSTEPS * B_ * GDIM];
__device__ uint32_t g_featSp[(size_t)B_ * NFEAT * ENC_Hc];     // 102 MB
__device__ uint32_t g_EmbSp[(size_t)TSTEPS * B_ * EMB_c];
__device__ uint32_t g_XSp[B_ * XDIM];
__device__ uint32_t g_HallSp[(size_t)TSTEPS * B_ * DEC_Hc];    // [t][b] rows
__device__ uint32_t g_WuSp[(size_t)ATTN_c * ENC_Hc];
__device__ uint32_t g_WihSp[(size_t)GDIM * EMB_c];
__device__ uint32_t g_WfcSp[(size_t)VOCAB_c * DEC_Hc];         // 131 MB
__device__ uint32_t g_WcatSp[(size_t)GDIM * XDIM];             // 48 MB

// ---------------- helpers ----------------------------------------------------
__device__ __forceinline__ uint32_t pack_bf2(__nv_bfloat16 a, __nv_bfloat16 b) {
    union { __nv_bfloat162 v; uint32_t u; } cv;
    cv.v.x = a; cv.v.y = b;
    return cv.u;
}
__device__ __forceinline__ void store_split(uint32_t* base, size_t row, int K,
                                            int k, float x0, float x1) {
    __nv_bfloat16 h0 = __float2bfloat16(x0);
    __nv_bfloat16 h1 = __float2bfloat16(x1);
    const float l0 = x0 - __bfloat162float(h0);
    const float l1 = x1 - __bfloat162float(h1);
    uint32_t* p = base + row * (size_t)K + ((k >> 5) << 5) + ((k & 31) >> 1);
    p[0]  = pack_bf2(h0, h1);
    p[16] = pack_bf2(__float2bfloat16(l0), __float2bfloat16(l1));
}
__device__ __forceinline__ void mma_bf16(float* c, uint32_t a0, uint32_t a1,
                                         uint32_t a2, uint32_t a3,
                                         uint32_t b0, uint32_t b1) {
    asm volatile(
        "mma.sync.aligned.m16n8k16.row.col.f32.bf16.bf16.f32 "
        "{%0,%1,%2,%3}, {%4,%5,%6,%7}, {%8,%9}, {%0,%1,%2,%3};"
        : "+f"(c[0]), "+f"(c[1]), "+f"(c[2]), "+f"(c[3])
        : "r"(a0), "r"(a1), "r"(a2), "r"(a3), "r"(b0), "r"(b1));
}
__device__ __forceinline__ void ldsm_x4(uint32_t& r0, uint32_t& r1,
                                        uint32_t& r2, uint32_t& r3,
                                        uint32_t addr) {
    asm volatile("ldmatrix.sync.aligned.m8n8.x4.shared.b16 {%0,%1,%2,%3}, [%4];"
                 : "=r"(r0), "=r"(r1), "=r"(r2), "=r"(r3) : "r"(addr));
}
__device__ __forceinline__ float tanh_fast(float x) {
    float y;
    asm("tanh.approx.f32 %0, %1;" : "=f"(y) : "f"(x));
    return y;
}
__device__ __forceinline__ uint32_t smem_u32(const void* p) {
    uint32_t a;
    asm("{ .reg .u64 t; cvta.to.shared.u64 t, %1; cvt.u32.u64 %0, t; }"
        : "=r"(a) : "l"(p));
    return a;
}
__device__ __forceinline__ void cp_async16(uint32_t dst, const void* src) {
    asm volatile("cp.async.cg.shared.global [%0], [%1], 16;"
                 :: "r"(dst), "l"(src));
}
#define CP_COMMIT() asm volatile("cp.async.commit_group;" ::: "memory")
#define CP_WAIT1()  asm volatile("cp.async.wait_group 1;" ::: "memory")

// ========== bf16x3 pipelined tensor GEMM with ldmatrix ======================
// tmap=1: output row r -> C + (r&63)*ldc + (r>>6)*VOCAB_c  ([b][t] layout)
template <int MT>
__global__ __launch_bounds__(256, 2)
void tg(const uint32_t* __restrict__ A32, int KA,
        const uint32_t* __restrict__ B32, int KB,
        const float* __restrict__ bias,
        float* __restrict__ C, int M, int N, int ldc, int kLen, int tmap)
{
    constexpr int WN = (MT == 128) ? 2 : 4;
    constexpr int NT = 128 / WN / 8;
    constexpr int NBAND = 128 / WN;
    constexpr int A_UNITS = MT * 8;
    constexpr int B_UNITS = 128 * 8;
    constexpr int NS = 3;
    constexpr int STAGE_B = (A_UNITS + B_UNITS) * 16;
    constexpr int APT = A_UNITS / 256;

    extern __shared__ uint32_t sm[];
    const uint32_t smBase = smem_u32(sm);

    const int tid = threadIdx.x;
    const int lane = tid & 31, wid = tid >> 5;
    const int warp_mi = wid / WN;
    const int warp_ni = wid % WN;
    const int rowBase = blockIdx.x * MT;
    const int colBase = blockIdx.y * 128;
    const int k0c = blockIdx.z * (kLen / 32);
    C += (size_t)blockIdx.z * M * ldc;

    float acc[2][NT][4];
#pragma unroll
    for (int mt = 0; mt < 2; mt++)
#pragma unroll
        for (int nt = 0; nt < NT; nt++)
#pragma unroll
            for (int q = 0; q < 4; q++) acc[mt][nt][q] = 0.f;

    const int nCh = kLen / 32;

    auto issueStage = [&](int ch) {
        const int s = ch % NS;
        const uint32_t aB = smBase + s * STAGE_B;
        const uint32_t bB = aB + A_UNITS * 16;
        const size_t srcC = (size_t)(k0c + ch) * 32;
#pragma unroll
        for (int i = 0; i < APT; i++) {
            const int w = tid * APT + i;
            const int row = w >> 3, u = w & 7;
            const uint32_t* src =
                A32 + (size_t)min(rowBase + row, M - 1) * KA + srcC + u * 4;
            cp_async16(aB + (uint32_t)(row * 8 + (u ^ (row & 7))) * 16, src);
        }
#pragma unroll
        for (int i = 0; i < 4; i++) {
            const int w = tid * 4 + i;
            const int row = w >> 3, u = w & 7;
            const uint32_t* src =
                B32 + (size_t)(colBase + row) * KB + srcC + u * 4;
            cp_async16(bB + (uint32_t)(row * 8 + (u ^ (row & 7))) * 16, src);
        }
        CP_COMMIT();
    };

    issueStage(0);
    issueStage(1);

    const int aRowL = (lane & 15);
    const int aUoff = (lane >> 4);
    const int bRowL = (lane & 7) + ((lane >> 4) << 3);
    const int bUoff = ((lane >> 3) & 1);

    for (int ch = 0; ch < nCh; ch++) {
        CP_WAIT1();
        __syncthreads();
        if (ch + 2 < nCh) issueStage(ch + 2); else CP_COMMIT();

        const int s = ch % NS;
        const uint32_t aB = smBase + s * STAGE_B;
        const uint32_t bB = aB + A_UNITS * 16;
#pragma unroll
        for (int t = 0; t < 2; t++) {
            uint32_t ah[2][4], al[2][4];
#pragma unroll
            for (int mt = 0; mt < 2; mt++) {
                const int r = warp_mi * 32 + mt * 16 + aRowL;
                const int uh = (2 * t + aUoff) ^ (r & 7);
                const int ul = (4 + 2 * t + aUoff) ^ (r & 7);
                ldsm_x4(ah[mt][0], ah[mt][1], ah[mt][2], ah[mt][3],
                        aB + (uint32_t)(r * 8 + uh) * 16);
                ldsm_x4(al[mt][0], al[mt][1], al[mt][2], al[mt][3],
                        aB + (uint32_t)(r * 8 + ul) * 16);
            }
#pragma unroll
            for (int np = 0; np < NT / 2; np++) {
                const int rb = warp_ni * NBAND + np * 16 + bRowL;
                const int uh = (2 * t + bUoff) ^ (rb & 7);
                const int ul = (4 + 2 * t + bUoff) ^ (rb & 7);
                uint32_t bh[4], bl[4];
                ldsm_x4(bh[0], bh[1], bh[2], bh[3],
                        bB + (uint32_t)(rb * 8 + uh) * 16);
                ldsm_x4(bl[0], bl[1], bl[2], bl[3],
                        bB + (uint32_t)(rb * 8 + ul) * 16);
#pragma unroll
                for (int half = 0; half < 2; half++) {
                    const int nt = np * 2 + half;
                    const uint32_t b0h = bh[half * 2], b1h = bh[half * 2 + 1];
                    const uint32_t b0l = bl[half * 2], b1l = bl[half * 2 + 1];
#pragma unroll
                    for (int mt = 0; mt < 2; mt++) {
                        mma_bf16(acc[mt][nt], ah[mt][0], ah[mt][1],
                                 ah[mt][2], ah[mt][3], b0h, b1h);
                        mma_bf16(acc[mt][nt], ah[mt][0], ah[mt][1],
                                 ah[mt][2], ah[mt][3], b0l, b1l);
                        mma_bf16(acc[mt][nt], al[mt][0], al[mt][1],
                                 al[mt][2], al[mt][3], b0h, b1h);
                    }
                }
            }
        }
    }

    // epilogue
#pragma unroll
    for (int mt = 0; mt < 2; mt++) {
#pragma unroll
        for (int nt = 0; nt < NT; nt++) {
            const int r0 = rowBase + warp_mi * 32 + mt * 16 + (lane >> 2);
            const int cc = colBase + warp_ni * NBAND + nt * 8 + (lane & 3) * 2;
            float bv0 = 0.f, bv1 = 0.f;
            if (bias) { bv0 = bias[cc]; bv1 = bias[cc + 1]; }
            if (r0 < M) {
                const size_t ro = tmap
                    ? (size_t)(r0 & 63) * ldc + (size_t)(r0 >> 6) * VOCAB_c
                    : (size_t)r0 * ldc;
                float2 v = { acc[mt][nt][0] + bv0, acc[mt][nt][1] + bv1 };
                *(float2*)&C[ro + cc] = v;
            }
            if (r0 + 8 < M) {
                const int r1 = r0 + 8;
                const size_t ro = tmap
                    ? (size_t)(r1 & 63) * ldc + (size_t)(r1 >> 6) * VOCAB_c
                    : (size_t)r1 * ldc;
                float2 v = { acc[mt][nt][2] + bv0, acc[mt][nt][3] + bv1 };
                *(float2*)&C[ro + cc] = v;
            }
        }
    }
}

// =========== transpose + split weights: in[K][N] -> out rows [N][K] =========
__global__ void ts_split(const float* __restrict__ in, int N,
                         uint32_t* __restrict__ out, int Ktot, int kOff)
{
    __shared__ float t[64][33];
    const int n0 = blockIdx.x * 32, k0 = blockIdx.y * 64;
    const int tx = threadIdx.x, ty = threadIdx.y;
    for (int i = ty; i < 64; i += 8)
        t[i][tx] = in[(size_t)(k0 + i) * N + n0 + tx];
    __syncthreads();
    for (int i = ty; i < 32; i += 8)
        store_split(out, n0 + tx, Ktot, kOff + k0 + 2 * i,
                    t[2 * i][tx], t[2 * i + 1][tx]);
}

// =========== row-major fp32 -> planar split (K = 2048 rows) =================
__global__ void row_split(const float* __restrict__ in,
                          uint32_t* __restrict__ out, size_t total)
{
    const size_t i = (size_t)blockIdx.x * blockDim.x + threadIdx.x;
    const size_t pos = i * 4;
    if (pos >= total) return;
    const float4 v = *(const float4*)(in + pos);
    const size_t row = pos >> 11;
    const int k = (int)(pos & 2047);
    store_split(out, row, 2048, k,     v.x, v.y);
    store_split(out, row, 2048, k + 2, v.z, v.w);
}

// =============== fp32 SGEMM (h0/c0 only, tiny) ==============================
__global__ __launch_bounds__(256, 2)
void sgemm128(const float* __restrict__ A, int lda,
              const float* __restrict__ Bm, int N, int K,
              const float* __restrict__ bias,
              float* __restrict__ C, int M)
{
    __shared__ float As[2][16][132];
    __shared__ float Bs[2][16][128];
    const int tid = threadIdx.x;
    const int bm = blockIdx.x, bn = blockIdx.y;
    const int aRow = tid >> 1, aK = (tid & 1) * 8;
    const int bRow = tid >> 4, bCol = (tid & 15) * 4;
    const int rowBase = bm * 128;
    const int aRowG = min(rowBase + aRow, M - 1);
    const float* Ap = A + (size_t)aRowG * lda + aK;
    const float* Bp = Bm + (size_t)bRow * N + (size_t)bn * 128 + bCol;
    const int ty = tid >> 4, tx = tid & 15;
    float acc[8][8];
#pragma unroll
    for (int i = 0; i < 8; i++)
#pragma unroll
        for (int j = 0; j < 8; j++) acc[i][j] = 0.f;
    const int nTiles = K / 16;
    float4 pa0, pa1, pb0, pb1;
    pa0 = *(const float4*)(Ap); pa1 = *(const float4*)(Ap + 4);
    pb0 = *(const float4*)(Bp); pb1 = *(const float4*)(Bp + 64);
    As[0][aK+0][aRow]=pa0.x; As[0][aK+1][aRow]=pa0.y;
    As[0][aK+2][aRow]=pa0.z; As[0][aK+3][aRow]=pa0.w;
    As[0][aK+4][aRow]=pa1.x; As[0][aK+5][aRow]=pa1.y;
    As[0][aK+6][aRow]=pa1.z; As[0][aK+7][aRow]=pa1.w;
    *(float4*)&Bs[0][bRow][bCol]      = pb0;
    *(float4*)&Bs[0][bRow][bCol + 64] = pb1;
    __syncthreads();
    for (int t = 0; t < nTiles; t++) {
        const int cur = t & 1, nxt = cur ^ 1;
        if (t + 1 < nTiles) {
            const float* Ap2 = Ap + (t + 1) * 16;
            const float* Bp2 = Bp + (size_t)(t + 1) * 16 * N;
            pa0 = *(const float4*)(Ap2); pa1 = *(const float4*)(Ap2 + 4);
            pb0 = *(const float4*)(Bp2); pb1 = *(const float4*)(Bp2 + 64);
        }
#pragma unroll
        for (int k = 0; k < 16; k++) {
            float a[8], b[8];
            *(float4*)&a[0] = *(const float4*)&As[cur][k][ty * 8];
            *(float4*)&a[4] = *(const float4*)&As[cur][k][ty * 8 + 4];
            *(float4*)&b[0] = *(const float4*)&Bs[cur][k][tx * 8];
            *(float4*)&b[4] = *(const float4*)&Bs[cur][k][tx * 8 + 4];
#pragma unroll
            for (int i = 0; i < 8; i++)
#pragma unroll
                for (int j = 0; j < 8; j++) acc[i][j] += a[i] * b[j];
        }
        if (t + 1 < nTiles) {
            As[nxt][aK+0][aRow]=pa0.x; As[nxt][aK+1][aRow]=pa0.y;
            As[nxt][aK+2][aRow]=pa0.z; As[nxt][aK+3][aRow]=pa0.w;
            As[nxt][aK+4][aRow]=pa1.x; As[nxt][aK+5][aRow]=pa1.y;
            As[nxt][aK+6][aRow]=pa1.z; As[nxt][aK+7][aRow]=pa1.w;
            *(float4*)&Bs[nxt][bRow][bCol]      = pb0;
            *(float4*)&Bs[nxt][bRow][bCol + 64] = pb1;
            __syncthreads();
        }
    }
    const int r0 = rowBase + ty * 8;
    const int c0 = bn * 128 + tx * 8;
#pragma unroll
    for (int i = 0; i < 8; i++) {
        const int r = r0 + i;
        if (r < M) {
#pragma unroll
            for (int j = 0; j < 8; j++)
                C[(size_t)r * N + c0 + j] = acc[i][j] + bias[c0 + j];
        }
    }
}

// ---------------- misc small kernels ----------------------------------------
__global__ void feat_mean_kernel(const float* __restrict__ f,
                                 float* __restrict__ out)
{
    const int b = blockIdx.x;
    const int k = blockIdx.y * 256 + threadIdx.x;
    float s = 0.f;
#pragma unroll 4
    for (int n = 0; n < NFEAT; n++)
        s += f[((size_t)b * NFEAT + n) * ENC_Hc + k];
    out[b * ENC_Hc + k] = s * (1.0f / (float)NFEAT);
}

__global__ void emb_gather_kernel(const int* __restrict__ captions,
                                  const float* __restrict__ table,
                                  uint32_t* __restrict__ embSp)
{
    const int m = blockIdx.x;
    const int t = m >> 6, b = m & 63;
    const int cap = captions[b * 32 + t];
    const float4* src = (const float4*)(table + (size_t)cap * EMB_c);
    for (int i = threadIdx.x; i < EMB_c / 4; i += blockDim.x) {
        const float4 v = src[i];
        store_split(embSp, m, EMB_c, 4 * i,     v.x, v.y);
        store_split(embSp, m, EMB_c, 4 * i + 2, v.z, v.w);
    }
}

__global__ void h0split_kernel(const float* __restrict__ h,
                               uint32_t* __restrict__ XSp)
{
    const int b = blockIdx.x, i = threadIdx.x;
    store_split(XSp, b, XDIM, ENC_Hc + 2 * i,
                h[b * DEC_Hc + 2 * i], h[b * DEC_Hc + 2 * i + 1]);
}

// ===== scores fused: hW (redundant per block) + tanh-dot; grid (64,7) =======
__global__ __launch_bounds__(256)
void scores_kernel(const float* __restrict__ Uf,
                   const float* __restrict__ h,
                   const float* __restrict__ Ww,
                   const float* __restrict__ bw,
                   const float* __restrict__ Wa,
                   float* __restrict__ scores)
{
    const int b = blockIdx.x, seg = blockIdx.y;
    const int tid = threadIdx.x;
    const int warp = tid >> 5, lane = tid & 31;
    __shared__ float sh[DEC_Hc];
    __shared__ float shw[ATTN_c];
    __shared__ float swa[ATTN_c];
    for (int j = tid; j < DEC_Hc; j += 256) sh[j] = h[b * DEC_Hc + j];
    for (int k = tid; k < ATTN_c; k += 256) swa[k] = Wa[k];
    __syncthreads();
    // hw for 2 columns per thread, 4 partial chains each
    {
        const int k0 = tid, k1 = tid + 256;
        float a0 = bw[k0], a1 = 0.f, a2 = 0.f, a3 = 0.f;
        float b0 = bw[k1], b1 = 0.f, b2 = 0.f, b3 = 0.f;
#pragma unroll 4
        for (int j = 0; j < DEC_Hc; j += 2) {
            const float h0 = sh[j], h1 = sh[j + 1];
            a0 += h0 * Ww[(size_t)j * ATTN_c + k0];
            b0 += h0 * Ww[(size_t)j * ATTN_c + k1];
            a1 += h1 * Ww[(size_t)(j + 1) * ATTN_c + k0];
            b1 += h1 * Ww[(size_t)(j + 1) * ATTN_c + k1];
        }
        shw[k0] = (a0 + a1) + (a2 + a3);
        shw[k1] = (b0 + b1) + (b2 + b3);
    }
    __syncthreads();
    for (int r = warp; r < 28; r += 8) {
        const int n = seg * 28 + r;
        const float* uf = Uf + ((size_t)b * NFEAT + n) * ATTN_c;
        float s = 0.f;
#pragma unroll 4
        for (int k = lane; k < ATTN_c; k += 32)
            s += tanh_fast(uf[k] + shw[k]) * swa[k];
#pragma unroll
        for (int o = 16; o; o >>= 1) s += __shfl_xor_sync(0xffffffffu, s, o);
        if (lane == 0) scores[b * NFEAT + n] = s;
    }
}

// ==== context fused: softmax(scores) + alpha@features -> XSp; grid (64,2) ===
__global__ __launch_bounds__(256)
void context_kernel(const float* __restrict__ feat,
                    const float* __restrict__ scores,
                    uint32_t* __restrict__ XSp,
                    float* __restrict__ outAttn)
{
    const int b = blockIdx.x, y = blockIdx.y, tid = threadIdx.x;
    __shared__ float sa[256];
    __shared__ float red[256];
    float v = (tid < NFEAT) ? scores[b * NFEAT + tid] : -INFINITY;
    red[tid] = v; __syncthreads();
    for (int o = 128; o; o >>= 1) {
        if (tid < o) red[tid] = fmaxf(red[tid], red[tid + o]);
        __syncthreads();
    }
    const float mx = red[0]; __syncthreads();
    const float e = (tid < NFEAT) ? __expf(v - mx) : 0.f;
    red[tid] = e; __syncthreads();
    for (int o = 128; o; o >>= 1) {
        if (tid < o) red[tid] += red[tid + o];
        __syncthreads();
    }
    const float inv = 1.f / red[0];
    sa[tid] = e * inv;
    if (y == 0 && outAttn && tid < NFEAT)
        outAttn[(size_t)b * TSTEPS * NFEAT + tid] = sa[tid];
    __syncthreads();

    // context: 4 cols per thread (float4), unroll 8 for MLP
    const int j = y * 1024 + tid * 4;
    float4 acc = {0.f, 0.f, 0.f, 0.f};
    const float* fb = feat + (size_t)b * NFEAT * ENC_Hc + j;
#pragma unroll 8
    for (int n = 0; n < NFEAT; n++) {
        const float al = sa[n];
        const float4 fv = *(const float4*)(fb + (size_t)n * ENC_Hc);
        acc.x += al * fv.x; acc.y += al * fv.y;
        acc.z += al * fv.z; acc.w += al * fv.w;
    }
    store_split(XSp, b, XDIM, j,     acc.x, acc.y);
    store_split(XSp, b, XDIM, j + 2, acc.z, acc.w);
}

// =============== LSTM pointwise: h, c, XSp tail, HallSp[t][b] ===============
__global__ void lstm_kernel(const float* __restrict__ P,
                            const float* __restrict__ GembT,
                            const float* __restrict__ bhh,
                            float* __restrict__ h,
                            float* __restrict__ c,
                            uint32_t* __restrict__ XSp,
                            uint32_t* __restrict__ HallSp, int t)
{
    const int b = blockIdx.x;
    const int j = blockIdx.y * 256 + threadIdx.x;
    const size_t ps = (size_t)B_ * GDIM;
    float g[4];
#pragma unroll
    for (int q = 0; q < 4; q++) {
        const int col = q * DEC_Hc + j;
        float s = GembT[(size_t)b * GDIM + col] + bhh[col];
#pragma unroll
        for (int z = 0; z < SPLITK_GATES; z++)
            s += P[z * ps + (size_t)b * GDIM + col];
        g[q] = s;
    }
    const float ig = 1.f / (1.f + __expf(-g[0]));
    const float fg = 1.f / (1.f + __expf(-g[1]));
    const float gg = tanhf(g[2]);
    const float og = 1.f / (1.f + __expf(-g[3]));
    const float cn = fg * c[b * DEC_Hc + j] + ig * gg;
    const float hn = og * tanhf(cn);
    c[b * DEC_Hc + j] = cn;
    h[b * DEC_Hc + j] = hn;
    const float hn1 = __shfl_down_sync(0xffffffffu, hn, 1);
    if ((j & 1) == 0) {
        store_split(HallSp, (size_t)t * B_ + b, DEC_Hc, j, hn, hn1);
        store_split(XSp, b, XDIM, ENC_Hc + j, hn, hn1);
    }
}

// ---------------------------------------------------------------------------
extern "C" void kernel_launch(void* const* d_in, const int* in_sizes, int n_in,
                              void* d_out, int out_size)
{
    const float* features = (const float*)d_in[0];
    const int*   captions = (const int*)d_in[1];
    const float* emb_tab  = (const float*)d_in[2];
    const float* W_u  = (const float*)d_in[3];
    const float* b_u  = (const float*)d_in[4];
    const float* W_w  = (const float*)d_in[5];
    const float* b_w  = (const float*)d_in[6];
    const float* W_a  = (const float*)d_in[7];
    const float* W_ih = (const float*)d_in[9];
    const float* b_ih = (const float*)d_in[10];
    const float* W_hh = (const float*)d_in[11];
    const float* b_hh = (const float*)d_in[12];
    const float* W_fc = (const float*)d_in[13];
    const float* b_fc = (const float*)d_in[14];
    const float* W_h0 = (const float*)d_in[15];
    const float* b_h0 = (const float*)d_in[16];
    const float* W_c0 = (const float*)d_in[17];
    const float* b_c0 = (const float*)d_in[18];

    float* outPred = (float*)d_out;
    const size_t predElems = (size_t)B_ * TSTEPS * VOCAB_c;
    const size_t attnElems = (size_t)B_ * TSTEPS * NFEAT;
    float* outAttn =
        ((size_t)out_size >= predElems + attnElems) ? outPred + predElems : nullptr;

    float *pUf, *pFM, *pH, *pC, *pSc, *pGP, *pGE;
    uint32_t *pFSp, *pESp, *pXSp, *pHSp, *pWuSp, *pWihSp, *pWfcSp, *pWcatSp;
    cudaGetSymbolAddress((void**)&pUf, g_Uf);
    cudaGetSymbolAddress((void**)&pFM, g_featmean);
    cudaGetSymbolAddress((void**)&pH,  g_h);
    cudaGetSymbolAddress((void**)&pC,  g_c);
    cudaGetSymbolAddress((void**)&pSc, g_scores);
    cudaGetSymbolAddress((void**)&pGP, g_GatesPart);
    cudaGetSymbolAddress((void**)&pGE, g_Gemb);
    cudaGetSymbolAddress((void**)&pFSp, g_featSp);
    cudaGetSymbolAddress((void**)&pESp, g_EmbSp);
    cudaGetSymbolAddress((void**)&pXSp, g_XSp);
    cudaGetSymbolAddress((void**)&pHSp, g_HallSp);
    cudaGetSymbolAddress((void**)&pWuSp,  g_WuSp);
    cudaGetSymbolAddress((void**)&pWihSp, g_WihSp);
    cudaGetSymbolAddress((void**)&pWfcSp, g_WfcSp);
    cudaGetSymbolAddress((void**)&pWcatSp, g_WcatSp);

    const int SM128 = 3 * (128 * 8 + 128 * 8) * 16;   // 98304
    const int SM64  = 3 * (64 * 8 + 128 * 8) * 16;    // 73728
    cudaFuncSetAttribute(tg<128>, cudaFuncAttributeMaxDynamicSharedMemorySize,
                         SM128);
    cudaFuncSetAttribute(tg<64>, cudaFuncAttributeMaxDynamicSharedMemorySize,
                         SM64);
    const dim3 tsb(32, 8);

    // side stream + events for overlapped 2-step logits chunks
    cudaStream_t side;
    cudaStreamCreateWithFlags(&side, cudaStreamNonBlocking);
    cudaEvent_t ev[20];
    for (int i = 0; i < 20; i++)
        cudaEventCreateWithFlags(&ev[i], cudaEventDisableTiming);

    // ---- prologue (launch #4 = context_kernel probe for ncu capture) ----
    row_split<<<(int)(((size_t)B_ * NFEAT * ENC_Hc / 4 + 255) / 256), 256>>>(
        features, pFSp, (size_t)B_ * NFEAT * ENC_Hc);                     // 1
    ts_split<<<dim3(ATTN_c / 32, ENC_Hc / 64), tsb>>>(W_u, ATTN_c, pWuSp,
                                                      ENC_Hc, 0);         // 2
    tg<128><<<dim3(B_ * NFEAT / 128, ATTN_c / 128, 1), 256, SM128>>>(
        pFSp, ENC_Hc, pWuSp, ENC_Hc, b_u, pUf, B_ * NFEAT, ATTN_c, ATTN_c,
        ENC_Hc, 0);                                                       // 3
    // probe: context on previous-replay scores state (deterministic; XSp
    // head overwritten by the real t=0 context below before gates read it)
    context_kernel<<<dim3(B_, 2), 256>>>(features, pSc, pXSp, nullptr);   // 4
    feat_mean_kernel<<<dim3(B_, ENC_Hc / 256), 256>>>(features, pFM);
    sgemm128<<<dim3(1, DEC_Hc / 128), 256>>>(pFM, ENC_Hc, W_h0, DEC_Hc,
                                             ENC_Hc, b_h0, pH, B_);
    sgemm128<<<dim3(1, DEC_Hc / 128), 256>>>(pFM, ENC_Hc, W_c0, DEC_Hc,
                                             ENC_Hc, b_c0, pC, B_);
    h0split_kernel<<<B_, 512>>>(pH, pXSp);
    ts_split<<<dim3(GDIM / 32, EMB_c / 64), tsb>>>(W_ih, GDIM, pWihSp,
                                                   EMB_c, 0);
    ts_split<<<dim3(VOCAB_c / 32, DEC_Hc / 64), tsb>>>(W_fc, VOCAB_c, pWfcSp,
                                                       DEC_Hc, 0);
    ts_split<<<dim3(GDIM / 32, ENC_Hc / 64), tsb>>>(W_ih + (size_t)EMB_c * GDIM,
                                                    GDIM, pWcatSp, XDIM, 0);
    ts_split<<<dim3(GDIM / 32, DEC_Hc / 64), tsb>>>(W_hh, GDIM, pWcatSp,
                                                    XDIM, ENC_Hc);
    emb_gather_kernel<<<TSTEPS * B_, 128>>>(captions, emb_tab, pESp);
    tg<128><<<dim3((TSTEPS * B_ + 127) / 128, GDIM / 128, 1), 256, SM128>>>(
        pESp, EMB_c, pWihSp, EMB_c, b_ih, pGE, TSTEPS * B_, GDIM, GDIM,
        EMB_c, 0);

    // fork: side stream joins capture after prologue (WfcSp ready)
    cudaEventRecord(ev[16], 0);
    cudaStreamWaitEvent(side, ev[16], 0);

    // ---- recurrence; logits in 2-step chunks on side stream ----
    for (int t = 0; t < TSTEPS; t++) {
        scores_kernel<<<dim3(B_, 7), 256>>>(pUf, pH, W_w, b_w, W_a, pSc);
        context_kernel<<<dim3(B_, 2), 256>>>(features, pSc, pXSp,
                                             outAttn ? outAttn +
                                                       (size_t)t * NFEAT
                                                     : nullptr);
        tg<64><<<dim3(1, GDIM / 128, SPLITK_GATES), 256, SM64>>>(
            pXSp, XDIM, pWcatSp, XDIM, nullptr, pGP,
            B_, GDIM, GDIM, XDIM / SPLITK_GATES, 0);
        lstm_kernel<<<dim3(B_, 4), 256>>>(pGP, pGE + (size_t)t * B_ * GDIM,
                                          b_hh, pH, pC, pXSp, pHSp, t);
        if ((t & 1) == 1) {
            // logits for steps t-1, t: [128,1024] @ WfcSp (one W read per 2)
            const int t0 = t - 1;
            const int ci = t0 >> 1;   // 0..14
            cudaEventRecord(ev[ci], 0);
            cudaStreamWaitEvent(side, ev[ci], 0);
            tg<128><<<dim3(1, VOCAB_c / 128, 1), 256, SM128, side>>>(
                pHSp + (size_t)t0 * B_ * DEC_Hc, DEC_Hc, pWfcSp, DEC_Hc,
                b_fc, outPred + (size_t)t0 * VOCAB_c, 2 * B_, VOCAB_c,
                TSTEPS * VOCAB_c, DEC_Hc, 1);
        }
    }
    // final chunk: step 30
    cudaEventRecord(ev[15], 0);
    cudaStreamWaitEvent(side, ev[15], 0);
    tg<64><<<dim3(1, VOCAB_c / 128, 1), 256, SM64, side>>>(
        pHSp + (size_t)30 * B_ * DEC_Hc, DEC_Hc, pWfcSp, DEC_Hc, b_fc,
        outPred + (size_t)30 * VOCAB_c, B_, VOCAB_c, TSTEPS * VOCAB_c,
        DEC_Hc, 1);

    // join side stream back into the primary stream
    cudaEventRecord(ev[17], side);
    cudaStreamWaitEvent(0, ev[17], 0);
}

// round 12
// speedup vs baseline: 1.2344x; 1.2344x over previous
#include <cuda_runtime.h>
#include <cuda_bf16.h>
#include <math.h>
#include <stdint.h>

// Problem constants
#define B_      64
#define NFEAT   196
#define ENC_Hc  2048
#define DEC_Hc  1024
#define ATTN_c  512
#define EMB_c   512
#define VOCAB_c 32000
#define TSTEPS  31
#define XDIM    (ENC_Hc + DEC_Hc)   // 3072
#define GDIM    (4 * DEC_Hc)        // 4096
#define SPLITK_GATES 8

// ---------------- scratch (device globals; no allocation allowed) -----------
__device__ float g_Uf[(size_t)B_ * NFEAT * ATTN_c];
__device__ float g_featmean[B_ * ENC_Hc];
__device__ float g_h[B_ * DEC_Hc];
__device__ float g_c[B_ * DEC_Hc];
__device__ float g_hw[B_ * ATTN_c];
__device__ float g_scores[B_ * NFEAT];
__device__ float g_GatesPart[SPLITK_GATES * B_ * GDIM];
__device__ float g_Gemb[(size_t)TSTEPS * B_ * GDIM];
__device__ uint32_t g_featSp[(size_t)B_ * NFEAT * ENC_Hc];     // 102 MB
__device__ uint32_t g_EmbSp[(size_t)TSTEPS * B_ * EMB_c];
__device__ uint32_t g_XSp[B_ * XDIM];
__device__ uint32_t g_HallSp[(size_t)TSTEPS * B_ * DEC_Hc];    // [t][b] rows
__device__ uint32_t g_WuSp[(size_t)ATTN_c * ENC_Hc];
__device__ uint32_t g_WihSp[(size_t)GDIM * EMB_c];
__device__ uint32_t g_WfcSp[(size_t)VOCAB_c * DEC_Hc];         // 131 MB
__device__ uint32_t g_WcatSp[(size_t)GDIM * XDIM];             // 48 MB

// ---------------- helpers ----------------------------------------------------
__device__ __forceinline__ uint32_t pack_bf2(__nv_bfloat16 a, __nv_bfloat16 b) {
    union { __nv_bfloat162 v; uint32_t u; } cv;
    cv.v.x = a; cv.v.y = b;
    return cv.u;
}
__device__ __forceinline__ void store_split(uint32_t* base, size_t row, int K,
                                            int k, float x0, float x1) {
    __nv_bfloat16 h0 = __float2bfloat16(x0);
    __nv_bfloat16 h1 = __float2bfloat16(x1);
    const float l0 = x0 - __bfloat162float(h0);
    const float l1 = x1 - __bfloat162float(h1);
    uint32_t* p = base + row * (size_t)K + ((k >> 5) << 5) + ((k & 31) >> 1);
    p[0]  = pack_bf2(h0, h1);
    p[16] = pack_bf2(__float2bfloat16(l0), __float2bfloat16(l1));
}
__device__ __forceinline__ void mma_bf16(float* c, uint32_t a0, uint32_t a1,
                                         uint32_t a2, uint32_t a3,
                                         uint32_t b0, uint32_t b1) {
    asm volatile(
        "mma.sync.aligned.m16n8k16.row.col.f32.bf16.bf16.f32 "
        "{%0,%1,%2,%3}, {%4,%5,%6,%7}, {%8,%9}, {%0,%1,%2,%3};"
        : "+f"(c[0]), "+f"(c[1]), "+f"(c[2]), "+f"(c[3])
        : "r"(a0), "r"(a1), "r"(a2), "r"(a3), "r"(b0), "r"(b1));
}
__device__ __forceinline__ void ldsm_x4(uint32_t& r0, uint32_t& r1,
                                        uint32_t& r2, uint32_t& r3,
                                        uint32_t addr) {
    asm volatile("ldmatrix.sync.aligned.m8n8.x4.shared.b16 {%0,%1,%2,%3}, [%4];"
                 : "=r"(r0), "=r"(r1), "=r"(r2), "=r"(r3) : "r"(addr));
}
__device__ __forceinline__ float tanh_fast(float x) {
    float y;
    asm("tanh.approx.f32 %0, %1;" : "=f"(y) : "f"(x));
    return y;
}
__device__ __forceinline__ uint32_t smem_u32(const void* p) {
    uint32_t a;
    asm("{ .reg .u64 t; cvta.to.shared.u64 t, %1; cvt.u32.u64 %0, t; }"
        : "=r"(a) : "l"(p));
    return a;
}
__device__ __forceinline__ void cp_async16(uint32_t dst, const void* src) {
    asm volatile("cp.async.cg.shared.global [%0], [%1], 16;"
                 :: "r"(dst), "l"(src));
}
#define CP_COMMIT() asm volatile("cp.async.commit_group;" ::: "memory")
#define CP_WAIT1()  asm volatile("cp.async.wait_group 1;" ::: "memory")

// ========== bf16x3 pipelined tensor GEMM with ldmatrix ======================
// tmap=1: output row r -> C + (r&63)*ldc + (r>>6)*VOCAB_c  ([b][t] layout)
template <int MT>
__global__ __launch_bounds__(256, 2)
void tg(const uint32_t* __restrict__ A32, int KA,
        const uint32_t* __restrict__ B32, int KB,
        const float* __restrict__ bias,
        float* __restrict__ C, int M, int N, int ldc, int kLen, int tmap)
{
    constexpr int WN = (MT == 128) ? 2 : 4;
    constexpr int NT = 128 / WN / 8;
    constexpr int NBAND = 128 / WN;
    constexpr int A_UNITS = MT * 8;
    constexpr int B_UNITS = 128 * 8;
    constexpr int NS = 3;
    constexpr int STAGE_B = (A_UNITS + B_UNITS) * 16;
    constexpr int APT = A_UNITS / 256;

    extern __shared__ uint32_t sm[];
    const uint32_t smBase = smem_u32(sm);

    const int tid = threadIdx.x;
    const int lane = tid & 31, wid = tid >> 5;
    const int warp_mi = wid / WN;
    const int warp_ni = wid % WN;
    const int rowBase = blockIdx.x * MT;
    const int colBase = blockIdx.y * 128;
    const int k0c = blockIdx.z * (kLen / 32);
    C += (size_t)blockIdx.z * M * ldc;

    float acc[2][NT][4];
#pragma unroll
    for (int mt = 0; mt < 2; mt++)
#pragma unroll
        for (int nt = 0; nt < NT; nt++)
#pragma unroll
            for (int q = 0; q < 4; q++) acc[mt][nt][q] = 0.f;

    const int nCh = kLen / 32;

    auto issueStage = [&](int ch) {
        const int s = ch % NS;
        const uint32_t aB = smBase + s * STAGE_B;
        const uint32_t bB = aB + A_UNITS * 16;
        const size_t srcC = (size_t)(k0c + ch) * 32;
#pragma unroll
        for (int i = 0; i < APT; i++) {
            const int w = tid * APT + i;
            const int row = w >> 3, u = w & 7;
            const uint32_t* src =
                A32 + (size_t)min(rowBase + row, M - 1) * KA + srcC + u * 4;
            cp_async16(aB + (uint32_t)(row * 8 + (u ^ (row & 7))) * 16, src);
        }
#pragma unroll
        for (int i = 0; i < 4; i++) {
            const int w = tid * 4 + i;
            const int row = w >> 3, u = w & 7;
            const uint32_t* src =
                B32 + (size_t)(colBase + row) * KB + srcC + u * 4;
            cp_async16(bB + (uint32_t)(row * 8 + (u ^ (row & 7))) * 16, src);
        }
        CP_COMMIT();
    };

    issueStage(0);
    issueStage(1);

    const int aRowL = (lane & 15);
    const int aUoff = (lane >> 4);
    const int bRowL = (lane & 7) + ((lane >> 4) << 3);
    const int bUoff = ((lane >> 3) & 1);

    for (int ch = 0; ch < nCh; ch++) {
        CP_WAIT1();
        __syncthreads();
        if (ch + 2 < nCh) issueStage(ch + 2); else CP_COMMIT();

        const int s = ch % NS;
        const uint32_t aB = smBase + s * STAGE_B;
        const uint32_t bB = aB + A_UNITS * 16;
#pragma unroll
        for (int t = 0; t < 2; t++) {
            uint32_t ah[2][4], al[2][4];
#pragma unroll
            for (int mt = 0; mt < 2; mt++) {
                const int r = warp_mi * 32 + mt * 16 + aRowL;
                const int uh = (2 * t + aUoff) ^ (r & 7);
                const int ul = (4 + 2 * t + aUoff) ^ (r & 7);
                ldsm_x4(ah[mt][0], ah[mt][1], ah[mt][2], ah[mt][3],
                        aB + (uint32_t)(r * 8 + uh) * 16);
                ldsm_x4(al[mt][0], al[mt][1], al[mt][2], al[mt][3],
                        aB + (uint32_t)(r * 8 + ul) * 16);
            }
#pragma unroll
            for (int np = 0; np < NT / 2; np++) {
                const int rb = warp_ni * NBAND + np * 16 + bRowL;
                const int uh = (2 * t + bUoff) ^ (rb & 7);
                const int ul = (4 + 2 * t + bUoff) ^ (rb & 7);
                uint32_t bh[4], bl[4];
                ldsm_x4(bh[0], bh[1], bh[2], bh[3],
                        bB + (uint32_t)(rb * 8 + uh) * 16);
                ldsm_x4(bl[0], bl[1], bl[2], bl[3],
                        bB + (uint32_t)(rb * 8 + ul) * 16);
#pragma unroll
                for (int half = 0; half < 2; half++) {
                    const int nt = np * 2 + half;
                    const uint32_t b0h = bh[half * 2], b1h = bh[half * 2 + 1];
                    const uint32_t b0l = bl[half * 2], b1l = bl[half * 2 + 1];
#pragma unroll
                    for (int mt = 0; mt < 2; mt++) {
                        mma_bf16(acc[mt][nt], ah[mt][0], ah[mt][1],
                                 ah[mt][2], ah[mt][3], b0h, b1h);
                        mma_bf16(acc[mt][nt], ah[mt][0], ah[mt][1],
                                 ah[mt][2], ah[mt][3], b0l, b1l);
                        mma_bf16(acc[mt][nt], al[mt][0], al[mt][1],
                                 al[mt][2], al[mt][3], b0h, b1h);
                    }
                }
            }
        }
    }

    // epilogue
#pragma unroll
    for (int mt = 0; mt < 2; mt++) {
#pragma unroll
        for (int nt = 0; nt < NT; nt++) {
            const int r0 = rowBase + warp_mi * 32 + mt * 16 + (lane >> 2);
            const int cc = colBase + warp_ni * NBAND + nt * 8 + (lane & 3) * 2;
            float bv0 = 0.f, bv1 = 0.f;
            if (bias) { bv0 = bias[cc]; bv1 = bias[cc + 1]; }
            if (r0 < M) {
                const size_t ro = tmap
                    ? (size_t)(r0 & 63) * ldc + (size_t)(r0 >> 6) * VOCAB_c
                    : (size_t)r0 * ldc;
                float2 v = { acc[mt][nt][0] + bv0, acc[mt][nt][1] + bv1 };
                *(float2*)&C[ro + cc] = v;
            }
            if (r0 + 8 < M) {
                const int r1 = r0 + 8;
                const size_t ro = tmap
                    ? (size_t)(r1 & 63) * ldc + (size_t)(r1 >> 6) * VOCAB_c
                    : (size_t)r1 * ldc;
                float2 v = { acc[mt][nt][2] + bv0, acc[mt][nt][3] + bv1 };
                *(float2*)&C[ro + cc] = v;
            }
        }
    }
}

// =========== transpose + split weights: in[K][N] -> out rows [N][K] =========
__global__ void ts_split(const float* __restrict__ in, int N,
                         uint32_t* __restrict__ out, int Ktot, int kOff)
{
    __shared__ float t[64][33];
    const int n0 = blockIdx.x * 32, k0 = blockIdx.y * 64;
    const int tx = threadIdx.x, ty = threadIdx.y;
    for (int i = ty; i < 64; i += 8)
        t[i][tx] = in[(size_t)(k0 + i) * N + n0 + tx];
    __syncthreads();
    for (int i = ty; i < 32; i += 8)
        store_split(out, n0 + tx, Ktot, kOff + k0 + 2 * i,
                    t[2 * i][tx], t[2 * i + 1][tx]);
}

// =========== row-major fp32 -> planar split (K = 2048 rows) =================
__global__ void row_split(const float* __restrict__ in,
                          uint32_t* __restrict__ out, size_t total)
{
    const size_t i = (size_t)blockIdx.x * blockDim.x + threadIdx.x;
    const size_t pos = i * 4;
    if (pos >= total) return;
    const float4 v = *(const float4*)(in + pos);
    const size_t row = pos >> 11;
    const int k = (int)(pos & 2047);
    store_split(out, row, 2048, k,     v.x, v.y);
    store_split(out, row, 2048, k + 2, v.z, v.w);
}

// =============== fp32 SGEMM (h0/c0 only, tiny) ==============================
__global__ __launch_bounds__(256, 2)
void sgemm128(const float* __restrict__ A, int lda,
              const float* __restrict__ Bm, int N, int K,
              const float* __restrict__ bias,
              float* __restrict__ C, int M)
{
    __shared__ float As[2][16][132];
    __shared__ float Bs[2][16][128];
    const int tid = threadIdx.x;
    const int bm = blockIdx.x, bn = blockIdx.y;
    const int aRow = tid >> 1, aK = (tid & 1) * 8;
    const int bRow = tid >> 4, bCol = (tid & 15) * 4;
    const int rowBase = bm * 128;
    const int aRowG = min(rowBase + aRow, M - 1);
    const float* Ap = A + (size_t)aRowG * lda + aK;
    const float* Bp = Bm + (size_t)bRow * N + (size_t)bn * 128 + bCol;
    const int ty = tid >> 4, tx = tid & 15;
    float acc[8][8];
#pragma unroll
    for (int i = 0; i < 8; i++)
#pragma unroll
        for (int j = 0; j < 8; j++) acc[i][j] = 0.f;
    const int nTiles = K / 16;
    float4 pa0, pa1, pb0, pb1;
    pa0 = *(const float4*)(Ap); pa1 = *(const float4*)(Ap + 4);
    pb0 = *(const float4*)(Bp); pb1 = *(const float4*)(Bp + 64);
    As[0][aK+0][aRow]=pa0.x; As[0][aK+1][aRow]=pa0.y;
    As[0][aK+2][aRow]=pa0.z; As[0][aK+3][aRow]=pa0.w;
    As[0][aK+4][aRow]=pa1.x; As[0][aK+5][aRow]=pa1.y;
    As[0][aK+6][aRow]=pa1.z; As[0][aK+7][aRow]=pa1.w;
    *(float4*)&Bs[0][bRow][bCol]      = pb0;
    *(float4*)&Bs[0][bRow][bCol + 64] = pb1;
    __syncthreads();
    for (int t = 0; t < nTiles; t++) {
        const int cur = t & 1, nxt = cur ^ 1;
        if (t + 1 < nTiles) {
            const float* Ap2 = Ap + (t + 1) * 16;
            const float* Bp2 = Bp + (size_t)(t + 1) * 16 * N;
            pa0 = *(const float4*)(Ap2); pa1 = *(const float4*)(Ap2 + 4);
            pb0 = *(const float4*)(Bp2); pb1 = *(const float4*)(Bp2 + 64);
        }
#pragma unroll
        for (int k = 0; k < 16; k++) {
            float a[8], b[8];
            *(float4*)&a[0] = *(const float4*)&As[cur][k][ty * 8];
            *(float4*)&a[4] = *(const float4*)&As[cur][k][ty * 8 + 4];
            *(float4*)&b[0] = *(const float4*)&Bs[cur][k][tx * 8];
            *(float4*)&b[4] = *(const float4*)&Bs[cur][k][tx * 8 + 4];
#pragma unroll
            for (int i = 0; i < 8; i++)
#pragma unroll
                for (int j = 0; j < 8; j++) acc[i][j] += a[i] * b[j];
        }
        if (t + 1 < nTiles) {
            As[nxt][aK+0][aRow]=pa0.x; As[nxt][aK+1][aRow]=pa0.y;
            As[nxt][aK+2][aRow]=pa0.z; As[nxt][aK+3][aRow]=pa0.w;
            As[nxt][aK+4][aRow]=pa1.x; As[nxt][aK+5][aRow]=pa1.y;
            As[nxt][aK+6][aRow]=pa1.z; As[nxt][aK+7][aRow]=pa1.w;
            *(float4*)&Bs[nxt][bRow][bCol]      = pb0;
            *(float4*)&Bs[nxt][bRow][bCol + 64] = pb1;
            __syncthreads();
        }
    }
    const int r0 = rowBase + ty * 8;
    const int c0 = bn * 128 + tx * 8;
#pragma unroll
    for (int i = 0; i < 8; i++) {
        const int r = r0 + i;
        if (r < M) {
#pragma unroll
            for (int j = 0; j < 8; j++)
                C[(size_t)r * N + c0 + j] = acc[i][j] + bias[c0 + j];
        }
    }
}

// ---------------- misc small kernels ----------------------------------------
__global__ void feat_mean_kernel(const float* __restrict__ f,
                                 float* __restrict__ out)
{
    const int b = blockIdx.x;
    const int k = blockIdx.y * 256 + threadIdx.x;
    float s = 0.f;
#pragma unroll 4
    for (int n = 0; n < NFEAT; n++)
        s += f[((size_t)b * NFEAT + n) * ENC_Hc + k];
    out[b * ENC_Hc + k] = s * (1.0f / (float)NFEAT);
}

__global__ void emb_gather_kernel(const int* __restrict__ captions,
                                  const float* __restrict__ table,
                                  uint32_t* __restrict__ embSp)
{
    const int m = blockIdx.x;
    const int t = m >> 6, b = m & 63;
    const int cap = captions[b * 32 + t];
    const float4* src = (const float4*)(table + (size_t)cap * EMB_c);
    for (int i = threadIdx.x; i < EMB_c / 4; i += blockDim.x) {
        const float4 v = src[i];
        store_split(embSp, m, EMB_c, 4 * i,     v.x, v.y);
        store_split(embSp, m, EMB_c, 4 * i + 2, v.z, v.w);
    }
}

__global__ void h0split_kernel(const float* __restrict__ h,
                               uint32_t* __restrict__ XSp)
{
    const int b = blockIdx.x, i = threadIdx.x;
    store_split(XSp, b, XDIM, ENC_Hc + 2 * i,
                h[b * DEC_Hc + 2 * i], h[b * DEC_Hc + 2 * i + 1]);
}

// =============== hW = h @ W_w + b_w   (grid 64 x 2, 256 thr) ================
__global__ __launch_bounds__(256)
void hw_kernel(const float* __restrict__ h,
               const float* __restrict__ Ww,
               const float* __restrict__ bw,
               float* __restrict__ hw)
{
    const int b = blockIdx.x;
    const int k = blockIdx.y * 256 + threadIdx.x;
    __shared__ float sh[DEC_Hc];
    for (int j = threadIdx.x; j < DEC_Hc; j += 256) sh[j] = h[b * DEC_Hc + j];
    __syncthreads();
    float s0 = bw[k], s1 = 0.f, s2 = 0.f, s3 = 0.f;
#pragma unroll 4
    for (int j = 0; j < DEC_Hc; j += 4) {
        s0 += sh[j + 0] * Ww[(size_t)(j + 0) * ATTN_c + k];
        s1 += sh[j + 1] * Ww[(size_t)(j + 1) * ATTN_c + k];
        s2 += sh[j + 2] * Ww[(size_t)(j + 2) * ATTN_c + k];
        s3 += sh[j + 3] * Ww[(size_t)(j + 3) * ATTN_c + k];
    }
    hw[b * ATTN_c + k] = (s0 + s1) + (s2 + s3);
}

// =============== scores: grid (64, 7), 256 thr ===============================
__global__ __launch_bounds__(256)
void scores_kernel(const float* __restrict__ Uf,
                   const float* __restrict__ hw,
                   const float* __restrict__ Wa,
                   float* __restrict__ scores)
{
    const int b = blockIdx.x, seg = blockIdx.y;
    const int tid = threadIdx.x;
    const int warp = tid >> 5, lane = tid & 31;
    __shared__ float shw[ATTN_c];
    __shared__ float swa[ATTN_c];
    for (int k = tid; k < ATTN_c; k += 256) {
        shw[k] = hw[b * ATTN_c + k];
        swa[k] = Wa[k];
    }
    __syncthreads();
    for (int r = warp; r < 28; r += 8) {
        const int n = seg * 28 + r;
        const float* uf = Uf + ((size_t)b * NFEAT + n) * ATTN_c;
        float s = 0.f;
#pragma unroll 4
        for (int k = lane; k < ATTN_c; k += 32)
            s += tanh_fast(uf[k] + shw[k]) * swa[k];
#pragma unroll
        for (int o = 16; o; o >>= 1) s += __shfl_xor_sync(0xffffffffu, s, o);
        if (lane == 0) scores[b * NFEAT + n] = s;
    }
}

// ==== context fused: softmax(scores) + alpha@features -> XSp; grid (64,2) ===
__global__ __launch_bounds__(256)
void context_kernel(const float* __restrict__ feat,
                    const float* __restrict__ scores,
                    uint32_t* __restrict__ XSp,
                    float* __restrict__ outAttn)
{
    const int b = blockIdx.x, y = blockIdx.y, tid = threadIdx.x;
    __shared__ float sa[256];
    __shared__ float red[256];
    float v = (tid < NFEAT) ? scores[b * NFEAT + tid] : -INFINITY;
    red[tid] = v; __syncthreads();
    for (int o = 128; o; o >>= 1) {
        if (tid < o) red[tid] = fmaxf(red[tid], red[tid + o]);
        __syncthreads();
    }
    const float mx = red[0]; __syncthreads();
    const float e = (tid < NFEAT) ? __expf(v - mx) : 0.f;
    red[tid] = e; __syncthreads();
    for (int o = 128; o; o >>= 1) {
        if (tid < o) red[tid] += red[tid + o];
        __syncthreads();
    }
    const float inv = 1.f / red[0];
    sa[tid] = e * inv;
    if (y == 0 && outAttn && tid < NFEAT)
        outAttn[(size_t)b * TSTEPS * NFEAT + tid] = sa[tid];
    __syncthreads();

    const int j = y * 1024 + tid * 4;
    float4 acc = {0.f, 0.f, 0.f, 0.f};
    const float* fb = feat + (size_t)b * NFEAT * ENC_Hc + j;
#pragma unroll 8
    for (int n = 0; n < NFEAT; n++) {
        const float al = sa[n];
        const float4 fv = *(const float4*)(fb + (size_t)n * ENC_Hc);
        acc.x += al * fv.x; acc.y += al * fv.y;
        acc.z += al * fv.z; acc.w += al * fv.w;
    }
    store_split(XSp, b, XDIM, j,     acc.x, acc.y);
    store_split(XSp, b, XDIM, j + 2, acc.z, acc.w);
}

// =============== LSTM pointwise: h, c, XSp tail, HallSp[t][b] ===============
__global__ void lstm_kernel(const float* __restrict__ P,
                            const float* __restrict__ GembT,
                            const float* __restrict__ bhh,
                            float* __restrict__ h,
                            float* __restrict__ c,
                            uint32_t* __restrict__ XSp,
                            uint32_t* __restrict__ HallSp, int t)
{
    const int b = blockIdx.x;
    const int j = blockIdx.y * 256 + threadIdx.x;
    const size_t ps = (size_t)B_ * GDIM;
    float g[4];
#pragma unroll
    for (int q = 0; q < 4; q++) {
        const int col = q * DEC_Hc + j;
        float s = GembT[(size_t)b * GDIM + col] + bhh[col];
#pragma unroll
        for (int z = 0; z < SPLITK_GATES; z++)
            s += P[z * ps + (size_t)b * GDIM + col];
        g[q] = s;
    }
    const float ig = 1.f / (1.f + __expf(-g[0]));
    const float fg = 1.f / (1.f + __expf(-g[1]));
    const float gg = tanhf(g[2]);
    const float og = 1.f / (1.f + __expf(-g[3]));
    const float cn = fg * c[b * DEC_Hc + j] + ig * gg;
    const float hn = og * tanhf(cn);
    c[b * DEC_Hc + j] = cn;
    h[b * DEC_Hc + j] = hn;
    const float hn1 = __shfl_down_sync(0xffffffffu, hn, 1);
    if ((j & 1) == 0) {
        store_split(HallSp, (size_t)t * B_ + b, DEC_Hc, j, hn, hn1);
        store_split(XSp, b, XDIM, ENC_Hc + j, hn, hn1);
    }
}

// ---------------------------------------------------------------------------
extern "C" void kernel_launch(void* const* d_in, const int* in_sizes, int n_in,
                              void* d_out, int out_size)
{
    const float* features = (const float*)d_in[0];
    const int*   captions = (const int*)d_in[1];
    const float* emb_tab  = (const float*)d_in[2];
    const float* W_u  = (const float*)d_in[3];
    const float* b_u  = (const float*)d_in[4];
    const float* W_w  = (const float*)d_in[5];
    const float* b_w  = (const float*)d_in[6];
    const float* W_a  = (const float*)d_in[7];
    const float* W_ih = (const float*)d_in[9];
    const float* b_ih = (const float*)d_in[10];
    const float* W_hh = (const float*)d_in[11];
    const float* b_hh = (const float*)d_in[12];
    const float* W_fc = (const float*)d_in[13];
    const float* b_fc = (const float*)d_in[14];
    const float* W_h0 = (const float*)d_in[15];
    const float* b_h0 = (const float*)d_in[16];
    const float* W_c0 = (const float*)d_in[17];
    const float* b_c0 = (const float*)d_in[18];

    float* outPred = (float*)d_out;
    const size_t predElems = (size_t)B_ * TSTEPS * VOCAB_c;
    const size_t attnElems = (size_t)B_ * TSTEPS * NFEAT;
    float* outAttn =
        ((size_t)out_size >= predElems + attnElems) ? outPred + predElems : nullptr;

    float *pUf, *pFM, *pH, *pC, *pHW, *pSc, *pGP, *pGE;
    uint32_t *pFSp, *pESp, *pXSp, *pHSp, *pWuSp, *pWihSp, *pWfcSp, *pWcatSp;
    cudaGetSymbolAddress((void**)&pUf, g_Uf);
    cudaGetSymbolAddress((void**)&pFM, g_featmean);
    cudaGetSymbolAddress((void**)&pH,  g_h);
    cudaGetSymbolAddress((void**)&pC,  g_c);
    cudaGetSymbolAddress((void**)&pHW, g_hw);
    cudaGetSymbolAddress((void**)&pSc, g_scores);
    cudaGetSymbolAddress((void**)&pGP, g_GatesPart);
    cudaGetSymbolAddress((void**)&pGE, g_Gemb);
    cudaGetSymbolAddress((void**)&pFSp, g_featSp);
    cudaGetSymbolAddress((void**)&pESp, g_EmbSp);
    cudaGetSymbolAddress((void**)&pXSp, g_XSp);
    cudaGetSymbolAddress((void**)&pHSp, g_HallSp);
    cudaGetSymbolAddress((void**)&pWuSp,  g_WuSp);
    cudaGetSymbolAddress((void**)&pWihSp, g_WihSp);
    cudaGetSymbolAddress((void**)&pWfcSp, g_WfcSp);
    cudaGetSymbolAddress((void**)&pWcatSp, g_WcatSp);

    const int SM128 = 3 * (128 * 8 + 128 * 8) * 16;   // 98304
    const int SM64  = 3 * (64 * 8 + 128 * 8) * 16;    // 73728
    cudaFuncSetAttribute(tg<128>, cudaFuncAttributeMaxDynamicSharedMemorySize,
                         SM128);
    cudaFuncSetAttribute(tg<64>, cudaFuncAttributeMaxDynamicSharedMemorySize,
                         SM64);
    const dim3 tsb(32, 8);

    // side stream + events for overlapped 2-step logits chunks
    cudaStream_t side;
    cudaStreamCreateWithFlags(&side, cudaStreamNonBlocking);
    cudaEvent_t ev[20];
    for (int i = 0; i < 20; i++)
        cudaEventCreateWithFlags(&ev[i], cudaEventDisableTiming);

    // ---- prologue (launch #4 = gates tg<64> probe for ncu capture) ----
    row_split<<<(int)(((size_t)B_ * NFEAT * ENC_Hc / 4 + 255) / 256), 256>>>(
        features, pFSp, (size_t)B_ * NFEAT * ENC_Hc);                     // 1
    ts_split<<<dim3(ATTN_c / 32, ENC_Hc / 64), tsb>>>(W_u, ATTN_c, pWuSp,
                                                      ENC_Hc, 0);         // 2
    tg<128><<<dim3(B_ * NFEAT / 128, ATTN_c / 128, 1), 256, SM128>>>(
        pFSp, ENC_Hc, pWuSp, ENC_Hc, b_u, pUf, B_ * NFEAT, ATTN_c, ATTN_c,
        ENC_Hc, 0);                                                       // 3
    // probe: gates GEMM on previous-replay XSp/WcatSp state (deterministic;
    // GatesPart overwritten by the real t=0 gates below)
    tg<64><<<dim3(1, GDIM / 128, SPLITK_GATES), 256, SM64>>>(
        pXSp, XDIM, pWcatSp, XDIM, nullptr, pGP,
        B_, GDIM, GDIM, XDIM / SPLITK_GATES, 0);                          // 4
    feat_mean_kernel<<<dim3(B_, ENC_Hc / 256), 256>>>(features, pFM);
    sgemm128<<<dim3(1, DEC_Hc / 128), 256>>>(pFM, ENC_Hc, W_h0, DEC_Hc,
                                             ENC_Hc, b_h0, pH, B_);
    sgemm128<<<dim3(1, DEC_Hc / 128), 256>>>(pFM, ENC_Hc, W_c0, DEC_Hc,
                                             ENC_Hc, b_c0, pC, B_);
    h0split_kernel<<<B_, 512>>>(pH, pXSp);
    ts_split<<<dim3(GDIM / 32, EMB_c / 64), tsb>>>(W_ih, GDIM, pWihSp,
                                                   EMB_c, 0);
    ts_split<<<dim3(VOCAB_c / 32, DEC_Hc / 64), tsb>>>(W_fc, VOCAB_c, pWfcSp,
                                                       DEC_Hc, 0);
    ts_split<<<dim3(GDIM / 32, ENC_Hc / 64), tsb>>>(W_ih + (size_t)EMB_c * GDIM,
                                                    GDIM, pWcatSp, XDIM, 0);
    ts_split<<<dim3(GDIM / 32, DEC_Hc / 64), tsb>>>(W_hh, GDIM, pWcatSp,
                                                    XDIM, ENC_Hc);
    emb_gather_kernel<<<TSTEPS * B_, 128>>>(captions, emb_tab, pESp);
    tg<128><<<dim3((TSTEPS * B_ + 127) / 128, GDIM / 128, 1), 256, SM128>>>(
        pESp, EMB_c, pWihSp, EMB_c, b_ih, pGE, TSTEPS * B_, GDIM, GDIM,
        EMB_c, 0);

    // fork: side stream joins capture after prologue (WfcSp ready)
    cudaEventRecord(ev[16], 0);
    cudaStreamWaitEvent(side, ev[16], 0);

    // ---- recurrence; logits in 2-step chunks on side stream ----
    for (int t = 0; t < TSTEPS; t++) {
        hw_kernel<<<dim3(B_, 2), 256>>>(pH, W_w, b_w, pHW);
        scores_kernel<<<dim3(B_, 7), 256>>>(pUf, pHW, W_a, pSc);
        context_kernel<<<dim3(B_, 2), 256>>>(features, pSc, pXSp,
                                             outAttn ? outAttn +
                                                       (size_t)t * NFEAT
                                                     : nullptr);
        tg<64><<<dim3(1, GDIM / 128, SPLITK_GATES), 256, SM64>>>(
            pXSp, XDIM, pWcatSp, XDIM, nullptr, pGP,
            B_, GDIM, GDIM, XDIM / SPLITK_GATES, 0);
        lstm_kernel<<<dim3(B_, 4), 256>>>(pGP, pGE + (size_t)t * B_ * GDIM,
                                          b_hh, pH, pC, pXSp, pHSp, t);
        if ((t & 1) == 1) {
            const int t0 = t - 1;
            const int ci = t0 >> 1;   // 0..14
            cudaEventRecord(ev[ci], 0);
            cudaStreamWaitEvent(side, ev[ci], 0);
            tg<128><<<dim3(1, VOCAB_c / 128, 1), 256, SM128, side>>>(
                pHSp + (size_t)t0 * B_ * DEC_Hc, DEC_Hc, pWfcSp, DEC_Hc,
                b_fc, outPred + (size_t)t0 * VOCAB_c, 2 * B_, VOCAB_c,
                TSTEPS * VOCAB_c, DEC_Hc, 1);
        }
    }
    // final chunk: step 30
    cudaEventRecord(ev[15], 0);
    cudaStreamWaitEvent(side, ev[15], 0);
    tg<64><<<dim3(1, VOCAB_c / 128, 1), 256, SM64, side>>>(
        pHSp + (size_t)30 * B_ * DEC_Hc, DEC_Hc, pWfcSp, DEC_Hc, b_fc,
        outPred + (size_t)30 * VOCAB_c, B_, VOCAB_c, TSTEPS * VOCAB_c,
        DEC_Hc, 1);

    // join side stream back into the primary stream
    cudaEventRecord(ev[17], side);
    cudaStreamWaitEvent(0, ev[17], 0);
}

// round 13
// speedup vs baseline: 1.3704x; 1.1102x over previous
#include <cuda_runtime.h>
#include <cuda_bf16.h>
#include <math.h>
#include <stdint.h>

// Problem constants
#define B_      64
#define NFEAT   196
#define ENC_Hc  2048
#define DEC_Hc  1024
#define ATTN_c  512
#define EMB_c   512
#define VOCAB_c 32000
#define TSTEPS  31
#define XDIM    (ENC_Hc + DEC_Hc)   // 3072
#define GDIM    (4 * DEC_Hc)        // 4096
#define SPLITK_GATES 8

// ---------------- scratch (device globals; no allocation allowed) -----------
__device__ float g_Uf[(size_t)B_ * NFEAT * ATTN_c];
__device__ float g_featmean[B_ * ENC_Hc];
__device__ float g_h[B_ * DEC_Hc];
__device__ float g_c[B_ * DEC_Hc];
__device__ float g_hw[B_ * ATTN_c];
__device__ float g_scores[B_ * NFEAT];
__device__ float g_GatesPart[SPLITK_GATES * B_ * GDIM];
__device__ float g_Gemb[(size_t)TSTEPS * B_ * GDIM];
__device__ uint32_t g_featSp[(size_t)B_ * NFEAT * ENC_Hc];     // 102 MB
__device__ uint32_t g_EmbSp[(size_t)TSTEPS * B_ * EMB_c];
__device__ uint32_t g_XSp[B_ * XDIM];
__device__ uint32_t g_HallSp[(size_t)TSTEPS * B_ * DEC_Hc];    // [t][b] rows
__device__ uint32_t g_WuSp[(size_t)ATTN_c * ENC_Hc];
__device__ uint32_t g_WihSp[(size_t)GDIM * EMB_c];
__device__ uint32_t g_WfcSp[(size_t)VOCAB_c * DEC_Hc];         // 131 MB
__device__ uint32_t g_WcatSp[(size_t)GDIM * XDIM];             // 48 MB

// ---------------- helpers ----------------------------------------------------
__device__ __forceinline__ uint32_t pack_bf2(__nv_bfloat16 a, __nv_bfloat16 b) {
    union { __nv_bfloat162 v; uint32_t u; } cv;
    cv.v.x = a; cv.v.y = b;
    return cv.u;
}
__device__ __forceinline__ void store_split(uint32_t* base, size_t row, int K,
                                            int k, float x0, float x1) {
    __nv_bfloat16 h0 = __float2bfloat16(x0);
    __nv_bfloat16 h1 = __float2bfloat16(x1);
    const float l0 = x0 - __bfloat162float(h0);
    const float l1 = x1 - __bfloat162float(h1);
    uint32_t* p = base + row * (size_t)K + ((k >> 5) << 5) + ((k & 31) >> 1);
    p[0]  = pack_bf2(h0, h1);
    p[16] = pack_bf2(__float2bfloat16(l0), __float2bfloat16(l1));
}
__device__ __forceinline__ void mma_bf16(float* c, uint32_t a0, uint32_t a1,
                                         uint32_t a2, uint32_t a3,
                                         uint32_t b0, uint32_t b1) {
    asm volatile(
        "mma.sync.aligned.m16n8k16.row.col.f32.bf16.bf16.f32 "
        "{%0,%1,%2,%3}, {%4,%5,%6,%7}, {%8,%9}, {%0,%1,%2,%3};"
        : "+f"(c[0]), "+f"(c[1]), "+f"(c[2]), "+f"(c[3])
        : "r"(a0), "r"(a1), "r"(a2), "r"(a3), "r"(b0), "r"(b1));
}
__device__ __forceinline__ void ldsm_x4(uint32_t& r0, uint32_t& r1,
                                        uint32_t& r2, uint32_t& r3,
                                        uint32_t addr) {
    asm volatile("ldmatrix.sync.aligned.m8n8.x4.shared.b16 {%0,%1,%2,%3}, [%4];"
                 : "=r"(r0), "=r"(r1), "=r"(r2), "=r"(r3) : "r"(addr));
}
__device__ __forceinline__ float tanh_fast(float x) {
    float y;
    asm("tanh.approx.f32 %0, %1;" : "=f"(y) : "f"(x));
    return y;
}
__device__ __forceinline__ uint32_t smem_u32(const void* p) {
    uint32_t a;
    asm("{ .reg .u64 t; cvta.to.shared.u64 t, %1; cvt.u32.u64 %0, t; }"
        : "=r"(a) : "l"(p));
    return a;
}
__device__ __forceinline__ void cp_async16(uint32_t dst, const void* src) {
    asm volatile("cp.async.cg.shared.global [%0], [%1], 16;"
                 :: "r"(dst), "l"(src));
}
#define CP_COMMIT() asm volatile("cp.async.commit_group;" ::: "memory")
#define CP_WAIT1()  asm volatile("cp.async.wait_group 1;" ::: "memory")

// ========== bf16x3 pipelined tensor GEMM with ldmatrix ======================
template <int MT>
__global__ __launch_bounds__(256, 2)
void tg(const uint32_t* __restrict__ A32, int KA,
        const uint32_t* __restrict__ B32, int KB,
        const float* __restrict__ bias,
        float* __restrict__ C, int M, int N, int ldc, int kLen)
{
    constexpr int WN = (MT == 128) ? 2 : 4;
    constexpr int NT = 128 / WN / 8;
    constexpr int NBAND = 128 / WN;
    constexpr int A_UNITS = MT * 8;
    constexpr int B_UNITS = 128 * 8;
    constexpr int NS = 3;
    constexpr int STAGE_B = (A_UNITS + B_UNITS) * 16;
    constexpr int APT = A_UNITS / 256;

    extern __shared__ uint32_t sm[];
    const uint32_t smBase = smem_u32(sm);

    const int tid = threadIdx.x;
    const int lane = tid & 31, wid = tid >> 5;
    const int warp_mi = wid / WN;
    const int warp_ni = wid % WN;
    const int rowBase = blockIdx.x * MT;
    const int colBase = blockIdx.y * 128;
    const int k0c = blockIdx.z * (kLen / 32);
    C += (size_t)blockIdx.z * M * ldc;

    float acc[2][NT][4];
#pragma unroll
    for (int mt = 0; mt < 2; mt++)
#pragma unroll
        for (int nt = 0; nt < NT; nt++)
#pragma unroll
            for (int q = 0; q < 4; q++) acc[mt][nt][q] = 0.f;

    const int nCh = kLen / 32;

    auto issueStage = [&](int ch) {
        const int s = ch % NS;
        const uint32_t aB = smBase + s * STAGE_B;
        const uint32_t bB = aB + A_UNITS * 16;
        const size_t srcC = (size_t)(k0c + ch) * 32;
#pragma unroll
        for (int i = 0; i < APT; i++) {
            const int w = tid * APT + i;
            const int row = w >> 3, u = w & 7;
            const uint32_t* src =
                A32 + (size_t)min(rowBase + row, M - 1) * KA + srcC + u * 4;
            cp_async16(aB + (uint32_t)(row * 8 + (u ^ (row & 7))) * 16, src);
        }
#pragma unroll
        for (int i = 0; i < 4; i++) {
            const int w = tid * 4 + i;
            const int row = w >> 3, u = w & 7;
            const uint32_t* src =
                B32 + (size_t)(colBase + row) * KB + srcC + u * 4;
            cp_async16(bB + (uint32_t)(row * 8 + (u ^ (row & 7))) * 16, src);
        }
        CP_COMMIT();
    };

    issueStage(0);
    issueStage(1);

    const int aRowL = (lane & 15);
    const int aUoff = (lane >> 4);
    const int bRowL = (lane & 7) + ((lane >> 4) << 3);
    const int bUoff = ((lane >> 3) & 1);

    for (int ch = 0; ch < nCh; ch++) {
        CP_WAIT1();
        __syncthreads();
        if (ch + 2 < nCh) issueStage(ch + 2); else CP_COMMIT();

        const int s = ch % NS;
        const uint32_t aB = smBase + s * STAGE_B;
        const uint32_t bB = aB + A_UNITS * 16;
#pragma unroll
        for (int t = 0; t < 2; t++) {
            uint32_t ah[2][4], al[2][4];
#pragma unroll
            for (int mt = 0; mt < 2; mt++) {
                const int r = warp_mi * 32 + mt * 16 + aRowL;
                const int uh = (2 * t + aUoff) ^ (r & 7);
                const int ul = (4 + 2 * t + aUoff) ^ (r & 7);
                ldsm_x4(ah[mt][0], ah[mt][1], ah[mt][2], ah[mt][3],
                        aB + (uint32_t)(r * 8 + uh) * 16);
                ldsm_x4(al[mt][0], al[mt][1], al[mt][2], al[mt][3],
                        aB + (uint32_t)(r * 8 + ul) * 16);
            }
#pragma unroll
            for (int np = 0; np < NT / 2; np++) {
                const int rb = warp_ni * NBAND + np * 16 + bRowL;
                const int uh = (2 * t + bUoff) ^ (rb & 7);
                const int ul = (4 + 2 * t + bUoff) ^ (rb & 7);
                uint32_t bh[4], bl[4];
                ldsm_x4(bh[0], bh[1], bh[2], bh[3],
                        bB + (uint32_t)(rb * 8 + uh) * 16);
                ldsm_x4(bl[0], bl[1], bl[2], bl[3],
                        bB + (uint32_t)(rb * 8 + ul) * 16);
#pragma unroll
                for (int half = 0; half < 2; half++) {
                    const int nt = np * 2 + half;
                    const uint32_t b0h = bh[half * 2], b1h = bh[half * 2 + 1];
                    const uint32_t b0l = bl[half * 2], b1l = bl[half * 2 + 1];
#pragma unroll
                    for (int mt = 0; mt < 2; mt++) {
                        mma_bf16(acc[mt][nt], ah[mt][0], ah[mt][1],
                                 ah[mt][2], ah[mt][3], b0h, b1h);
                        mma_bf16(acc[mt][nt], ah[mt][0], ah[mt][1],
                                 ah[mt][2], ah[mt][3], b0l, b1l);
                        mma_bf16(acc[mt][nt], al[mt][0], al[mt][1],
                                 al[mt][2], al[mt][3], b0h, b1h);
                    }
                }
            }
        }
    }

    // epilogue
#pragma unroll
    for (int mt = 0; mt < 2; mt++) {
#pragma unroll
        for (int nt = 0; nt < NT; nt++) {
            const int r0 = rowBase + warp_mi * 32 + mt * 16 + (lane >> 2);
            const int cc = colBase + warp_ni * NBAND + nt * 8 + (lane & 3) * 2;
            float bv0 = 0.f, bv1 = 0.f;
            if (bias) { bv0 = bias[cc]; bv1 = bias[cc + 1]; }
            if (r0 < M) {
                float2 v = { acc[mt][nt][0] + bv0, acc[mt][nt][1] + bv1 };
                *(float2*)&C[(size_t)r0 * ldc + cc] = v;
            }
            if (r0 + 8 < M) {
                float2 v = { acc[mt][nt][2] + bv0, acc[mt][nt][3] + bv1 };
                *(float2*)&C[(size_t)(r0 + 8) * ldc + cc] = v;
            }
        }
    }
}

// =========== transpose + split weights: in[K][N] -> out rows [N][K] =========
__global__ void ts_split(const float* __restrict__ in, int N,
                         uint32_t* __restrict__ out, int Ktot, int kOff)
{
    __shared__ float t[64][33];
    const int n0 = blockIdx.x * 32, k0 = blockIdx.y * 64;
    const int tx = threadIdx.x, ty = threadIdx.y;
    for (int i = ty; i < 64; i += 8)
        t[i][tx] = in[(size_t)(k0 + i) * N + n0 + tx];
    __syncthreads();
    for (int i = ty; i < 32; i += 8)
        store_split(out, n0 + tx, Ktot, kOff + k0 + 2 * i,
                    t[2 * i][tx], t[2 * i + 1][tx]);
}

// =========== row-major fp32 -> planar split (K = 2048 rows) =================
__global__ void row_split(const float* __restrict__ in,
                          uint32_t* __restrict__ out, size_t total)
{
    const size_t i = (size_t)blockIdx.x * blockDim.x + threadIdx.x;
    const size_t pos = i * 4;
    if (pos >= total) return;
    const float4 v = *(const float4*)(in + pos);
    const size_t row = pos >> 11;
    const int k = (int)(pos & 2047);
    store_split(out, row, 2048, k,     v.x, v.y);
    store_split(out, row, 2048, k + 2, v.z, v.w);
}

// =============== fp32 SGEMM (h0/c0 only, tiny) ==============================
__global__ __launch_bounds__(256, 2)
void sgemm128(const float* __restrict__ A, int lda,
              const float* __restrict__ Bm, int N, int K,
              const float* __restrict__ bias,
              float* __restrict__ C, int M)
{
    __shared__ float As[2][16][132];
    __shared__ float Bs[2][16][128];
    const int tid = threadIdx.x;
    const int bm = blockIdx.x, bn = blockIdx.y;
    const int aRow = tid >> 1, aK = (tid & 1) * 8;
    const int bRow = tid >> 4, bCol = (tid & 15) * 4;
    const int rowBase = bm * 128;
    const int aRowG = min(rowBase + aRow, M - 1);
    const float* Ap = A + (size_t)aRowG * lda + aK;
    const float* Bp = Bm + (size_t)bRow * N + (size_t)bn * 128 + bCol;
    const int ty = tid >> 4, tx = tid & 15;
    float acc[8][8];
#pragma unroll
    for (int i = 0; i < 8; i++)
#pragma unroll
        for (int j = 0; j < 8; j++) acc[i][j] = 0.f;
    const int nTiles = K / 16;
    float4 pa0, pa1, pb0, pb1;
    pa0 = *(const float4*)(Ap); pa1 = *(const float4*)(Ap + 4);
    pb0 = *(const float4*)(Bp); pb1 = *(const float4*)(Bp + 64);
    As[0][aK+0][aRow]=pa0.x; As[0][aK+1][aRow]=pa0.y;
    As[0][aK+2][aRow]=pa0.z; As[0][aK+3][aRow]=pa0.w;
    As[0][aK+4][aRow]=pa1.x; As[0][aK+5][aRow]=pa1.y;
    As[0][aK+6][aRow]=pa1.z; As[0][aK+7][aRow]=pa1.w;
    *(float4*)&Bs[0][bRow][bCol]      = pb0;
    *(float4*)&Bs[0][bRow][bCol + 64] = pb1;
    __syncthreads();
    for (int t = 0; t < nTiles; t++) {
        const int cur = t & 1, nxt = cur ^ 1;
        if (t + 1 < nTiles) {
            const float* Ap2 = Ap + (t + 1) * 16;
            const float* Bp2 = Bp + (size_t)(t + 1) * 16 * N;
            pa0 = *(const float4*)(Ap2); pa1 = *(const float4*)(Ap2 + 4);
            pb0 = *(const float4*)(Bp2); pb1 = *(const float4*)(Bp2 + 64);
        }
#pragma unroll
        for (int k = 0; k < 16; k++) {
            float a[8], b[8];
            *(float4*)&a[0] = *(const float4*)&As[cur][k][ty * 8];
            *(float4*)&a[4] = *(const float4*)&As[cur][k][ty * 8 + 4];
            *(float4*)&b[0] = *(const float4*)&Bs[cur][k][tx * 8];
            *(float4*)&b[4] = *(const float4*)&Bs[cur][k][tx * 8 + 4];
#pragma unroll
            for (int i = 0; i < 8; i++)
#pragma unroll
                for (int j = 0; j < 8; j++) acc[i][j] += a[i] * b[j];
        }
        if (t + 1 < nTiles) {
            As[nxt][aK+0][aRow]=pa0.x; As[nxt][aK+1][aRow]=pa0.y;
            As[nxt][aK+2][aRow]=pa0.z; As[nxt][aK+3][aRow]=pa0.w;
            As[nxt][aK+4][aRow]=pa1.x; As[nxt][aK+5][aRow]=pa1.y;
            As[nxt][aK+6][aRow]=pa1.z; As[nxt][aK+7][aRow]=pa1.w;
            *(float4*)&Bs[nxt][bRow][bCol]      = pb0;
            *(float4*)&Bs[nxt][bRow][bCol + 64] = pb1;
            __syncthreads();
        }
    }
    const int r0 = rowBase + ty * 8;
    const int c0 = bn * 128 + tx * 8;
#pragma unroll
    for (int i = 0; i < 8; i++) {
        const int r = r0 + i;
        if (r < M) {
#pragma unroll
            for (int j = 0; j < 8; j++)
                C[(size_t)r * N + c0 + j] = acc[i][j] + bias[c0 + j];
        }
    }
}

// ---------------- misc small kernels ----------------------------------------
__global__ void feat_mean_kernel(const float* __restrict__ f,
                                 float* __restrict__ out)
{
    const int b = blockIdx.x;
    const int k = blockIdx.y * 256 + threadIdx.x;
    float s = 0.f;
#pragma unroll 4
    for (int n = 0; n < NFEAT; n++)
        s += f[((size_t)b * NFEAT + n) * ENC_Hc + k];
    out[b * ENC_Hc + k] = s * (1.0f / (float)NFEAT);
}

__global__ void emb_gather_kernel(const int* __restrict__ captions,
                                  const float* __restrict__ table,
                                  uint32_t* __restrict__ embSp)
{
    const int m = blockIdx.x;
    const int t = m >> 6, b = m & 63;
    const int cap = captions[b * 32 + t];
    const float4* src = (const float4*)(table + (size_t)cap * EMB_c);
    for (int i = threadIdx.x; i < EMB_c / 4; i += blockDim.x) {
        const float4 v = src[i];
        store_split(embSp, m, EMB_c, 4 * i,     v.x, v.y);
        store_split(embSp, m, EMB_c, 4 * i + 2, v.z, v.w);
    }
}

__global__ void h0split_kernel(const float* __restrict__ h,
                               uint32_t* __restrict__ XSp)
{
    const int b = blockIdx.x, i = threadIdx.x;
    store_split(XSp, b, XDIM, ENC_Hc + 2 * i,
                h[b * DEC_Hc + 2 * i], h[b * DEC_Hc + 2 * i + 1]);
}

// =============== hW = h @ W_w + b_w   (grid 64 x 2, 256 thr) ================
__global__ __launch_bounds__(256)
void hw_kernel(const float* __restrict__ h,
               const float* __restrict__ Ww,
               const float* __restrict__ bw,
               float* __restrict__ hw)
{
    const int b = blockIdx.x;
    const int k = blockIdx.y * 256 + threadIdx.x;
    __shared__ float sh[DEC_Hc];
    for (int j = threadIdx.x; j < DEC_Hc; j += 256) sh[j] = h[b * DEC_Hc + j];
    __syncthreads();
    float s0 = bw[k], s1 = 0.f, s2 = 0.f, s3 = 0.f;
#pragma unroll 4
    for (int j = 0; j < DEC_Hc; j += 4) {
        s0 += sh[j + 0] * Ww[(size_t)(j + 0) * ATTN_c + k];
        s1 += sh[j + 1] * Ww[(size_t)(j + 1) * ATTN_c + k];
        s2 += sh[j + 2] * Ww[(size_t)(j + 2) * ATTN_c + k];
        s3 += sh[j + 3] * Ww[(size_t)(j + 3) * ATTN_c + k];
    }
    hw[b * ATTN_c + k] = (s0 + s1) + (s2 + s3);
}

// =============== scores: grid (64, 7), 256 thr ===============================
__global__ __launch_bounds__(256)
void scores_kernel(const float* __restrict__ Uf,
                   const float* __restrict__ hw,
                   const float* __restrict__ Wa,
                   float* __restrict__ scores)
{
    const int b = blockIdx.x, seg = blockIdx.y;
    const int tid = threadIdx.x;
    const int warp = tid >> 5, lane = tid & 31;
    __shared__ float shw[ATTN_c];
    __shared__ float swa[ATTN_c];
    for (int k = tid; k < ATTN_c; k += 256) {
        shw[k] = hw[b * ATTN_c + k];
        swa[k] = Wa[k];
    }
    __syncthreads();
    for (int r = warp; r < 28; r += 8) {
        const int n = seg * 28 + r;
        const float* uf = Uf + ((size_t)b * NFEAT + n) * ATTN_c;
        float s = 0.f;
#pragma unroll 4
        for (int k = lane; k < ATTN_c; k += 32)
            s += tanh_fast(uf[k] + shw[k]) * swa[k];
#pragma unroll
        for (int o = 16; o; o >>= 1) s += __shfl_xor_sync(0xffffffffu, s, o);
        if (lane == 0) scores[b * NFEAT + n] = s;
    }
}

// ==== context fused: softmax(scores) + alpha@features -> XSp; grid (64,4) ===
__global__ __launch_bounds__(256)
void context_kernel(const float* __restrict__ feat,
                    const float* __restrict__ scores,
                    uint32_t* __restrict__ XSp,
                    float* __restrict__ outAttn)
{
    const int b = blockIdx.x, y = blockIdx.y, tid = threadIdx.x;
    __shared__ float sa[256];
    __shared__ float red[256];
    float v = (tid < NFEAT) ? scores[b * NFEAT + tid] : -INFINITY;
    red[tid] = v; __syncthreads();
    for (int o = 128; o; o >>= 1) {
        if (tid < o) red[tid] = fmaxf(red[tid], red[tid + o]);
        __syncthreads();
    }
    const float mx = red[0]; __syncthreads();
    const float e = (tid < NFEAT) ? __expf(v - mx) : 0.f;
    red[tid] = e; __syncthreads();
    for (int o = 128; o; o >>= 1) {
        if (tid < o) red[tid] += red[tid + o];
        __syncthreads();
    }
    const float inv = 1.f / red[0];
    sa[tid] = e * inv;
    if (y == 0 && outAttn && tid < NFEAT)
        outAttn[(size_t)b * TSTEPS * NFEAT + tid] = sa[tid];
    __syncthreads();

    // context: 2 cols per thread (float2), unroll 8 — R10 geometry
    const int j = y * 512 + tid * 2;
    float s0 = 0.f, s1 = 0.f;
    const float* fb = feat + (size_t)b * NFEAT * ENC_Hc + j;
#pragma unroll 8
    for (int n = 0; n < NFEAT; n++) {
        const float al = sa[n];
        const float2 fv = *(const float2*)(fb + (size_t)n * ENC_Hc);
        s0 += al * fv.x; s1 += al * fv.y;
    }
    store_split(XSp, b, XDIM, j, s0, s1);
}

// =============== LSTM pointwise: h, c, XSp tail, HallSp[t][b] ===============
__global__ void lstm_kernel(const float* __restrict__ P,
                            const float* __restrict__ GembT,
                            const float* __restrict__ bhh,
                            float* __restrict__ h,
                            float* __restrict__ c,
                            uint32_t* __restrict__ XSp,
                            uint32_t* __restrict__ HallSp, int t)
{
    const int b = blockIdx.x;
    const int j = blockIdx.y * 256 + threadIdx.x;
    const size_t ps = (size_t)B_ * GDIM;
    float g[4];
#pragma unroll
    for (int q = 0; q < 4; q++) {
        const int col = q * DEC_Hc + j;
        float s = GembT[(size_t)b * GDIM + col] + bhh[col];
#pragma unroll
        for (int z = 0; z < SPLITK_GATES; z++)
            s += P[z * ps + (size_t)b * GDIM + col];
        g[q] = s;
    }
    const float ig = 1.f / (1.f + __expf(-g[0]));
    const float fg = 1.f / (1.f + __expf(-g[1]));
    const float gg = tanhf(g[2]);
    const float og = 1.f / (1.f + __expf(-g[3]));
    const float cn = fg * c[b * DEC_Hc + j] + ig * gg;
    const float hn = og * tanhf(cn);
    c[b * DEC_Hc + j] = cn;
    h[b * DEC_Hc + j] = hn;
    const float hn1 = __shfl_down_sync(0xffffffffu, hn, 1);
    if ((j & 1) == 0) {
        store_split(HallSp, (size_t)t * B_ + b, DEC_Hc, j, hn, hn1);
        store_split(XSp, b, XDIM, ENC_Hc + j, hn, hn1);
    }
}

// ---------------------------------------------------------------------------
extern "C" void kernel_launch(void* const* d_in, const int* in_sizes, int n_in,
                              void* d_out, int out_size)
{
    const float* features = (const float*)d_in[0];
    const int*   captions = (const int*)d_in[1];
    const float* emb_tab  = (const float*)d_in[2];
    const float* W_u  = (const float*)d_in[3];
    const float* b_u  = (const float*)d_in[4];
    const float* W_w  = (const float*)d_in[5];
    const float* b_w  = (const float*)d_in[6];
    const float* W_a  = (const float*)d_in[7];
    const float* W_ih = (const float*)d_in[9];
    const float* b_ih = (const float*)d_in[10];
    const float* W_hh = (const float*)d_in[11];
    const float* b_hh = (const float*)d_in[12];
    const float* W_fc = (const float*)d_in[13];
    const float* b_fc = (const float*)d_in[14];
    const float* W_h0 = (const float*)d_in[15];
    const float* b_h0 = (const float*)d_in[16];
    const float* W_c0 = (const float*)d_in[17];
    const float* b_c0 = (const float*)d_in[18];

    float* outPred = (float*)d_out;
    const size_t predElems = (size_t)B_ * TSTEPS * VOCAB_c;
    const size_t attnElems = (size_t)B_ * TSTEPS * NFEAT;
    float* outAttn =
        ((size_t)out_size >= predElems + attnElems) ? outPred + predElems : nullptr;

    float *pUf, *pFM, *pH, *pC, *pHW, *pSc, *pGP, *pGE;
    uint32_t *pFSp, *pESp, *pXSp, *pHSp, *pWuSp, *pWihSp, *pWfcSp, *pWcatSp;
    cudaGetSymbolAddress((void**)&pUf, g_Uf);
    cudaGetSymbolAddress((void**)&pFM, g_featmean);
    cudaGetSymbolAddress((void**)&pH,  g_h);
    cudaGetSymbolAddress((void**)&pC,  g_c);
    cudaGetSymbolAddress((void**)&pHW, g_hw);
    cudaGetSymbolAddress((void**)&pSc, g_scores);
    cudaGetSymbolAddress((void**)&pGP, g_GatesPart);
    cudaGetSymbolAddress((void**)&pGE, g_Gemb);
    cudaGetSymbolAddress((void**)&pFSp, g_featSp);
    cudaGetSymbolAddress((void**)&pESp, g_EmbSp);
    cudaGetSymbolAddress((void**)&pXSp, g_XSp);
    cudaGetSymbolAddress((void**)&pHSp, g_HallSp);
    cudaGetSymbolAddress((void**)&pWuSp,  g_WuSp);
    cudaGetSymbolAddress((void**)&pWihSp, g_WihSp);
    cudaGetSymbolAddress((void**)&pWfcSp, g_WfcSp);
    cudaGetSymbolAddress((void**)&pWcatSp, g_WcatSp);

    const int SM128 = 3 * (128 * 8 + 128 * 8) * 16;   // 98304
    const int SM64  = 3 * (64 * 8 + 128 * 8) * 16;    // 73728
    cudaFuncSetAttribute(tg<128>, cudaFuncAttributeMaxDynamicSharedMemorySize,
                         SM128);
    cudaFuncSetAttribute(tg<64>, cudaFuncAttributeMaxDynamicSharedMemorySize,
                         SM64);
    const dim3 tsb(32, 8);

    cudaStream_t side;
    cudaStreamCreateWithFlags(&side, cudaStreamNonBlocking);
    cudaEvent_t evStep[TSTEPS];
    for (int i = 0; i < TSTEPS; i++)
        cudaEventCreateWithFlags(&evStep[i], cudaEventDisableTiming);
    cudaEvent_t evFork, evPro, evJoin;
    cudaEventCreateWithFlags(&evFork, cudaEventDisableTiming);
    cudaEventCreateWithFlags(&evPro,  cudaEventDisableTiming);
    cudaEventCreateWithFlags(&evJoin, cudaEventDisableTiming);

    // ---- fork side stream at the very start ----
    cudaEventRecord(evFork, 0);
    cudaStreamWaitEvent(side, evFork, 0);

    // side stream: Wfc split + h0/c0 chain (independent of main prologue)
    ts_split<<<dim3(VOCAB_c / 32, DEC_Hc / 64), tsb, 0, side>>>(
        W_fc, VOCAB_c, pWfcSp, DEC_Hc, 0);
    feat_mean_kernel<<<dim3(B_, ENC_Hc / 256), 256, 0, side>>>(features, pFM);
    sgemm128<<<dim3(1, DEC_Hc / 128), 256, 0, side>>>(
        pFM, ENC_Hc, W_h0, DEC_Hc, ENC_Hc, b_h0, pH, B_);
    sgemm128<<<dim3(1, DEC_Hc / 128), 256, 0, side>>>(
        pFM, ENC_Hc, W_c0, DEC_Hc, ENC_Hc, b_c0, pC, B_);
    h0split_kernel<<<B_, 512, 0, side>>>(pH, pXSp);
    cudaEventRecord(evPro, side);

    // main stream prologue (launch #4 on main = context probe)
    row_split<<<(int)(((size_t)B_ * NFEAT * ENC_Hc / 4 + 255) / 256), 256>>>(
        features, pFSp, (size_t)B_ * NFEAT * ENC_Hc);                     // 1
    ts_split<<<dim3(ATTN_c / 32, ENC_Hc / 64), tsb>>>(W_u, ATTN_c, pWuSp,
                                                      ENC_Hc, 0);         // 2
    tg<128><<<dim3(B_ * NFEAT / 128, ATTN_c / 128, 1), 256, SM128>>>(
        pFSp, ENC_Hc, pWuSp, ENC_Hc, b_u, pUf, B_ * NFEAT, ATTN_c, ATTN_c,
        ENC_Hc);                                                          // 3
    // probe: fused context on previous-replay scores (deterministic; XSp
    // head overwritten by real t=0 context before gates read it)
    context_kernel<<<dim3(B_, ENC_Hc / 512), 256>>>(features, pSc, pXSp,
                                                    nullptr);             // 4
    ts_split<<<dim3(GDIM / 32, EMB_c / 64), tsb>>>(W_ih, GDIM, pWihSp,
                                                   EMB_c, 0);
    ts_split<<<dim3(GDIM / 32, ENC_Hc / 64), tsb>>>(W_ih + (size_t)EMB_c * GDIM,
                                                    GDIM, pWcatSp, XDIM, 0);
    ts_split<<<dim3(GDIM / 32, DEC_Hc / 64), tsb>>>(W_hh, GDIM, pWcatSp,
                                                    XDIM, ENC_Hc);
    emb_gather_kernel<<<TSTEPS * B_, 128>>>(captions, emb_tab, pESp);
    tg<128><<<dim3((TSTEPS * B_ + 127) / 128, GDIM / 128, 1), 256, SM128>>>(
        pESp, EMB_c, pWihSp, EMB_c, b_ih, pGE, TSTEPS * B_, GDIM, GDIM,
        EMB_c);

    // main waits for h0/c0/XSp-tail from side before entering the loop
    cudaStreamWaitEvent(0, evPro, 0);

    // ---- recurrence; per-step logits overlapped on side stream ----
    for (int t = 0; t < TSTEPS; t++) {
        hw_kernel<<<dim3(B_, 2), 256>>>(pH, W_w, b_w, pHW);
        scores_kernel<<<dim3(B_, 7), 256>>>(pUf, pHW, W_a, pSc);
        context_kernel<<<dim3(B_, ENC_Hc / 512), 256>>>(
            features, pSc, pXSp,
            outAttn ? outAttn + (size_t)t * NFEAT : nullptr);
        tg<64><<<dim3(1, GDIM / 128, SPLITK_GATES), 256, SM64>>>(
            pXSp, XDIM, pWcatSp, XDIM, nullptr, pGP,
            B_, GDIM, GDIM, XDIM / SPLITK_GATES);
        lstm_kernel<<<dim3(B_, 4), 256>>>(pGP, pGE + (size_t)t * B_ * GDIM,
                                          b_hh, pH, pC, pXSp, pHSp, t);
        cudaEventRecord(evStep[t], 0);
        cudaStreamWaitEvent(side, evStep[t], 0);
        // logits rows for step t: [64,1024] @ WfcSp -> preds[:, t, :]
        tg<64><<<dim3(1, VOCAB_c / 128, 1), 256, SM64, side>>>(
            pHSp + (size_t)t * B_ * DEC_Hc, DEC_Hc, pWfcSp, DEC_Hc, b_fc,
            outPred + (size_t)t * VOCAB_c, B_, VOCAB_c, TSTEPS * VOCAB_c,
            DEC_Hc);
    }

    // join side stream back into the primary stream
    cudaEventRecord(evJoin, side);
    cudaStreamWaitEvent(0, evJoin, 0);
}

// round 14
// speedup vs baseline: 1.4134x; 1.0314x over previous
#include <cuda_runtime.h>
#include <cuda_bf16.h>
#include <math.h>
#include <stdint.h>

// Problem constants
#define B_      64
#define NFEAT   196
#define ENC_Hc  2048
#define DEC_Hc  1024
#define ATTN_c  512
#define EMB_c   512
#define VOCAB_c 32000
#define TSTEPS  31
#define XDIM    (ENC_Hc + DEC_Hc)   // 3072
#define GDIM    (4 * DEC_Hc)        // 4096
#define SPLITK_GATES 8

// ---------------- scratch (device globals; no allocation allowed) -----------
__device__ float g_Uf[(size_t)B_ * NFEAT * ATTN_c];
__device__ float g_featmean[B_ * ENC_Hc];
__device__ float g_h[B_ * DEC_Hc];
__device__ float g_c[B_ * DEC_Hc];
__device__ float g_hw[B_ * ATTN_c];
__device__ float g_scores[B_ * NFEAT];
__device__ float g_GatesPart[SPLITK_GATES * B_ * GDIM];
__device__ float g_Gemb[(size_t)TSTEPS * B_ * GDIM];
__device__ uint32_t g_featSp[(size_t)B_ * NFEAT * ENC_Hc];     // 102 MB
__device__ uint32_t g_EmbSp[(size_t)TSTEPS * B_ * EMB_c];
__device__ uint32_t g_XSp[B_ * XDIM];
__device__ uint32_t g_HallSp[(size_t)TSTEPS * B_ * DEC_Hc];    // [t][b] rows
__device__ uint32_t g_WuSp[(size_t)ATTN_c * ENC_Hc];
__device__ uint32_t g_WihSp[(size_t)GDIM * EMB_c];
__device__ uint32_t g_WfcSp[(size_t)VOCAB_c * DEC_Hc];         // 131 MB
__device__ uint32_t g_WcatSp[(size_t)GDIM * XDIM];             // 48 MB

// ---------------- helpers ----------------------------------------------------
__device__ __forceinline__ uint32_t pack_bf2(__nv_bfloat16 a, __nv_bfloat16 b) {
    union { __nv_bfloat162 v; uint32_t u; } cv;
    cv.v.x = a; cv.v.y = b;
    return cv.u;
}
__device__ __forceinline__ void store_split(uint32_t* base, size_t row, int K,
                                            int k, float x0, float x1) {
    __nv_bfloat16 h0 = __float2bfloat16(x0);
    __nv_bfloat16 h1 = __float2bfloat16(x1);
    const float l0 = x0 - __bfloat162float(h0);
    const float l1 = x1 - __bfloat162float(h1);
    uint32_t* p = base + row * (size_t)K + ((k >> 5) << 5) + ((k & 31) >> 1);
    p[0]  = pack_bf2(h0, h1);
    p[16] = pack_bf2(__float2bfloat16(l0), __float2bfloat16(l1));
}
__device__ __forceinline__ void mma_bf16(float* c, uint32_t a0, uint32_t a1,
                                         uint32_t a2, uint32_t a3,
                                         uint32_t b0, uint32_t b1) {
    asm volatile(
        "mma.sync.aligned.m16n8k16.row.col.f32.bf16.bf16.f32 "
        "{%0,%1,%2,%3}, {%4,%5,%6,%7}, {%8,%9}, {%0,%1,%2,%3};"
        : "+f"(c[0]), "+f"(c[1]), "+f"(c[2]), "+f"(c[3])
        : "r"(a0), "r"(a1), "r"(a2), "r"(a3), "r"(b0), "r"(b1));
}
__device__ __forceinline__ void ldsm_x4(uint32_t& r0, uint32_t& r1,
                                        uint32_t& r2, uint32_t& r3,
                                        uint32_t addr) {
    asm volatile("ldmatrix.sync.aligned.m8n8.x4.shared.b16 {%0,%1,%2,%3}, [%4];"
                 : "=r"(r0), "=r"(r1), "=r"(r2), "=r"(r3) : "r"(addr));
}
__device__ __forceinline__ float tanh_fast(float x) {
    float y;
    asm("tanh.approx.f32 %0, %1;" : "=f"(y) : "f"(x));
    return y;
}
__device__ __forceinline__ uint32_t smem_u32(const void* p) {
    uint32_t a;
    asm("{ .reg .u64 t; cvta.to.shared.u64 t, %1; cvt.u32.u64 %0, t; }"
        : "=r"(a) : "l"(p));
    return a;
}
__device__ __forceinline__ void cp_async16(uint32_t dst, const void* src) {
    asm volatile("cp.async.cg.shared.global [%0], [%1], 16;"
                 :: "r"(dst), "l"(src));
}
#define CP_COMMIT() asm volatile("cp.async.commit_group;" ::: "memory")
#define CP_WAIT1()  asm volatile("cp.async.wait_group 1;" ::: "memory")

// ========== bf16x3 pipelined tensor GEMM with ldmatrix ======================
template <int MT>
__global__ __launch_bounds__(256, 2)
void tg(const uint32_t* __restrict__ A32, int KA,
        const uint32_t* __restrict__ B32, int KB,
        const float* __restrict__ bias,
        float* __restrict__ C, int M, int N, int ldc, int kLen)
{
    constexpr int WN = (MT == 128) ? 2 : 4;
    constexpr int NT = 128 / WN / 8;
    constexpr int NBAND = 128 / WN;
    constexpr int A_UNITS = MT * 8;
    constexpr int B_UNITS = 128 * 8;
    constexpr int NS = 3;
    constexpr int STAGE_B = (A_UNITS + B_UNITS) * 16;
    constexpr int APT = A_UNITS / 256;

    extern __shared__ uint32_t sm[];
    const uint32_t smBase = smem_u32(sm);

    const int tid = threadIdx.x;
    const int lane = tid & 31, wid = tid >> 5;
    const int warp_mi = wid / WN;
    const int warp_ni = wid % WN;
    const int rowBase = blockIdx.x * MT;
    const int colBase = blockIdx.y * 128;
    const int k0c = blockIdx.z * (kLen / 32);
    C += (size_t)blockIdx.z * M * ldc;

    float acc[2][NT][4];
#pragma unroll
    for (int mt = 0; mt < 2; mt++)
#pragma unroll
        for (int nt = 0; nt < NT; nt++)
#pragma unroll
            for (int q = 0; q < 4; q++) acc[mt][nt][q] = 0.f;

    const int nCh = kLen / 32;

    auto issueStage = [&](int ch) {
        const int s = ch % NS;
        const uint32_t aB = smBase + s * STAGE_B;
        const uint32_t bB = aB + A_UNITS * 16;
        const size_t srcC = (size_t)(k0c + ch) * 32;
#pragma unroll
        for (int i = 0; i < APT; i++) {
            const int w = tid * APT + i;
            const int row = w >> 3, u = w & 7;
            const uint32_t* src =
                A32 + (size_t)min(rowBase + row, M - 1) * KA + srcC + u * 4;
            cp_async16(aB + (uint32_t)(row * 8 + (u ^ (row & 7))) * 16, src);
        }
#pragma unroll
        for (int i = 0; i < 4; i++) {
            const int w = tid * 4 + i;
            const int row = w >> 3, u = w & 7;
            const uint32_t* src =
                B32 + (size_t)(colBase + row) * KB + srcC + u * 4;
            cp_async16(bB + (uint32_t)(row * 8 + (u ^ (row & 7))) * 16, src);
        }
        CP_COMMIT();
    };

    issueStage(0);
    issueStage(1);

    const int aRowL = (lane & 15);
    const int aUoff = (lane >> 4);
    const int bRowL = (lane & 7) + ((lane >> 4) << 3);
    const int bUoff = ((lane >> 3) & 1);

    for (int ch = 0; ch < nCh; ch++) {
        CP_WAIT1();
        __syncthreads();
        if (ch + 2 < nCh) issueStage(ch + 2); else CP_COMMIT();

        const int s = ch % NS;
        const uint32_t aB = smBase + s * STAGE_B;
        const uint32_t bB = aB + A_UNITS * 16;
#pragma unroll
        for (int t = 0; t < 2; t++) {
            uint32_t ah[2][4], al[2][4];
#pragma unroll
            for (int mt = 0; mt < 2; mt++) {
                const int r = warp_mi * 32 + mt * 16 + aRowL;
                const int uh = (2 * t + aUoff) ^ (r & 7);
                const int ul = (4 + 2 * t + aUoff) ^ (r & 7);
                ldsm_x4(ah[mt][0], ah[mt][1], ah[mt][2], ah[mt][3],
                        aB + (uint32_t)(r * 8 + uh) * 16);
                ldsm_x4(al[mt][0], al[mt][1], al[mt][2], al[mt][3],
                        aB + (uint32_t)(r * 8 + ul) * 16);
            }
#pragma unroll
            for (int np = 0; np < NT / 2; np++) {
                const int rb = warp_ni * NBAND + np * 16 + bRowL;
                const int uh = (2 * t + bUoff) ^ (rb & 7);
                const int ul = (4 + 2 * t + bUoff) ^ (rb & 7);
                uint32_t bh[4], bl[4];
                ldsm_x4(bh[0], bh[1], bh[2], bh[3],
                        bB + (uint32_t)(rb * 8 + uh) * 16);
                ldsm_x4(bl[0], bl[1], bl[2], bl[3],
                        bB + (uint32_t)(rb * 8 + ul) * 16);
#pragma unroll
                for (int half = 0; half < 2; half++) {
                    const int nt = np * 2 + half;
                    const uint32_t b0h = bh[half * 2], b1h = bh[half * 2 + 1];
                    const uint32_t b0l = bl[half * 2], b1l = bl[half * 2 + 1];
#pragma unroll
                    for (int mt = 0; mt < 2; mt++) {
                        mma_bf16(acc[mt][nt], ah[mt][0], ah[mt][1],
                                 ah[mt][2], ah[mt][3], b0h, b1h);
                        mma_bf16(acc[mt][nt], ah[mt][0], ah[mt][1],
                                 ah[mt][2], ah[mt][3], b0l, b1l);
                        mma_bf16(acc[mt][nt], al[mt][0], al[mt][1],
                                 al[mt][2], al[mt][3], b0h, b1h);
                    }
                }
            }
        }
    }

    // epilogue
#pragma unroll
    for (int mt = 0; mt < 2; mt++) {
#pragma unroll
        for (int nt = 0; nt < NT; nt++) {
            const int r0 = rowBase + warp_mi * 32 + mt * 16 + (lane >> 2);
            const int cc = colBase + warp_ni * NBAND + nt * 8 + (lane & 3) * 2;
            float bv0 = 0.f, bv1 = 0.f;
            if (bias) { bv0 = bias[cc]; bv1 = bias[cc + 1]; }
            if (r0 < M) {
                float2 v = { acc[mt][nt][0] + bv0, acc[mt][nt][1] + bv1 };
                *(float2*)&C[(size_t)r0 * ldc + cc] = v;
            }
            if (r0 + 8 < M) {
                float2 v = { acc[mt][nt][2] + bv0, acc[mt][nt][3] + bv1 };
                *(float2*)&C[(size_t)(r0 + 8) * ldc + cc] = v;
            }
        }
    }
}

// =========== transpose + split weights: in[K][N] -> out rows [N][K] =========
__global__ void ts_split(const float* __restrict__ in, int N,
                         uint32_t* __restrict__ out, int Ktot, int kOff)
{
    __shared__ float t[64][33];
    const int n0 = blockIdx.x * 32, k0 = blockIdx.y * 64;
    const int tx = threadIdx.x, ty = threadIdx.y;
    for (int i = ty; i < 64; i += 8)
        t[i][tx] = in[(size_t)(k0 + i) * N + n0 + tx];
    __syncthreads();
    for (int i = ty; i < 32; i += 8)
        store_split(out, n0 + tx, Ktot, kOff + k0 + 2 * i,
                    t[2 * i][tx], t[2 * i + 1][tx]);
}

// =========== row-major fp32 -> planar split (K = 2048 rows) =================
__global__ void row_split(const float* __restrict__ in,
                          uint32_t* __restrict__ out, size_t total)
{
    const size_t i = (size_t)blockIdx.x * blockDim.x + threadIdx.x;
    const size_t pos = i * 4;
    if (pos >= total) return;
    const float4 v = *(const float4*)(in + pos);
    const size_t row = pos >> 11;
    const int k = (int)(pos & 2047);
    store_split(out, row, 2048, k,     v.x, v.y);
    store_split(out, row, 2048, k + 2, v.z, v.w);
}

// ---------------- misc small kernels ----------------------------------------
__global__ void feat_mean_kernel(const float* __restrict__ f,
                                 float* __restrict__ out)
{
    const int b = blockIdx.x;
    const int k = blockIdx.y * 256 + threadIdx.x;
    float s = 0.f;
#pragma unroll 4
    for (int n = 0; n < NFEAT; n++)
        s += f[((size_t)b * NFEAT + n) * ENC_Hc + k];
    out[b * ENC_Hc + k] = s * (1.0f / (float)NFEAT);
}

__global__ void emb_gather_kernel(const int* __restrict__ captions,
                                  const float* __restrict__ table,
                                  uint32_t* __restrict__ embSp)
{
    const int m = blockIdx.x;
    const int t = m >> 6, b = m & 63;
    const int cap = captions[b * 32 + t];
    const float4* src = (const float4*)(table + (size_t)cap * EMB_c);
    for (int i = threadIdx.x; i < EMB_c / 4; i += blockDim.x) {
        const float4 v = src[i];
        store_split(embSp, m, EMB_c, 4 * i,     v.x, v.y);
        store_split(embSp, m, EMB_c, 4 * i + 2, v.z, v.w);
    }
}

// ===== fused h0/c0 GEMV: grid (64, 4), 256 thr; writes h, c, XSp tail =======
__global__ __launch_bounds__(256)
void hc0_kernel(const float* __restrict__ fm,
                const float* __restrict__ Wh0, const float* __restrict__ bh0,
                const float* __restrict__ Wc0, const float* __restrict__ bc0,
                float* __restrict__ h, float* __restrict__ c,
                uint32_t* __restrict__ XSp)
{
    const int b = blockIdx.x;
    const int col = blockIdx.y * 256 + threadIdx.x;
    __shared__ float sf[ENC_Hc];
    for (int j = threadIdx.x; j < ENC_Hc; j += 256)
        sf[j] = fm[b * ENC_Hc + j];
    __syncthreads();
    float h0 = bh0[col], h1 = 0.f;
    float c0 = bc0[col], c1 = 0.f;
#pragma unroll 4
    for (int j = 0; j < ENC_Hc; j += 2) {
        const float f0 = sf[j], f1 = sf[j + 1];
        h0 += f0 * Wh0[(size_t)j * DEC_Hc + col];
        h1 += f1 * Wh0[(size_t)(j + 1) * DEC_Hc + col];
        c0 += f0 * Wc0[(size_t)j * DEC_Hc + col];
        c1 += f1 * Wc0[(size_t)(j + 1) * DEC_Hc + col];
    }
    const float hv = h0 + h1;
    const float cv = c0 + c1;
    h[b * DEC_Hc + col] = hv;
    c[b * DEC_Hc + col] = cv;
    const float hv1 = __shfl_down_sync(0xffffffffu, hv, 1);
    if ((col & 1) == 0)
        store_split(XSp, b, XDIM, ENC_Hc + col, hv, hv1);
}

// =============== hW = h @ W_w + b_w   (grid 64 x 2, 256 thr) ================
__global__ __launch_bounds__(256)
void hw_kernel(const float* __restrict__ h,
               const float* __restrict__ Ww,
               const float* __restrict__ bw,
               float* __restrict__ hw)
{
    const int b = blockIdx.x;
    const int k = blockIdx.y * 256 + threadIdx.x;
    __shared__ float sh[DEC_Hc];
    for (int j = threadIdx.x; j < DEC_Hc; j += 256) sh[j] = h[b * DEC_Hc + j];
    __syncthreads();
    float s0 = bw[k], s1 = 0.f, s2 = 0.f, s3 = 0.f;
#pragma unroll 4
    for (int j = 0; j < DEC_Hc; j += 4) {
        s0 += sh[j + 0] * Ww[(size_t)(j + 0) * ATTN_c + k];
        s1 += sh[j + 1] * Ww[(size_t)(j + 1) * ATTN_c + k];
        s2 += sh[j + 2] * Ww[(size_t)(j + 2) * ATTN_c + k];
        s3 += sh[j + 3] * Ww[(size_t)(j + 3) * ATTN_c + k];
    }
    hw[b * ATTN_c + k] = (s0 + s1) + (s2 + s3);
}

// =============== scores: grid (64, 7), 256 thr ===============================
__global__ __launch_bounds__(256)
void scores_kernel(const float* __restrict__ Uf,
                   const float* __restrict__ hw,
                   const float* __restrict__ Wa,
                   float* __restrict__ scores)
{
    const int b = blockIdx.x, seg = blockIdx.y;
    const int tid = threadIdx.x;
    const int warp = tid >> 5, lane = tid & 31;
    __shared__ float shw[ATTN_c];
    __shared__ float swa[ATTN_c];
    for (int k = tid; k < ATTN_c; k += 256) {
        shw[k] = hw[b * ATTN_c + k];
        swa[k] = Wa[k];
    }
    __syncthreads();
    for (int r = warp; r < 28; r += 8) {
        const int n = seg * 28 + r;
        const float* uf = Uf + ((size_t)b * NFEAT + n) * ATTN_c;
        float s = 0.f;
#pragma unroll 4
        for (int k = lane; k < ATTN_c; k += 32)
            s += tanh_fast(uf[k] + shw[k]) * swa[k];
#pragma unroll
        for (int o = 16; o; o >>= 1) s += __shfl_xor_sync(0xffffffffu, s, o);
        if (lane == 0) scores[b * NFEAT + n] = s;
    }
}

// ==== context fused: softmax(scores) + alpha@features -> XSp; grid (64,4) ===
__global__ __launch_bounds__(256)
void context_kernel(const float* __restrict__ feat,
                    const float* __restrict__ scores,
                    uint32_t* __restrict__ XSp,
                    float* __restrict__ outAttn)
{
    const int b = blockIdx.x, y = blockIdx.y, tid = threadIdx.x;
    __shared__ float sa[256];
    __shared__ float red[256];
    float v = (tid < NFEAT) ? scores[b * NFEAT + tid] : -INFINITY;
    red[tid] = v; __syncthreads();
    for (int o = 128; o; o >>= 1) {
        if (tid < o) red[tid] = fmaxf(red[tid], red[tid + o]);
        __syncthreads();
    }
    const float mx = red[0]; __syncthreads();
    const float e = (tid < NFEAT) ? __expf(v - mx) : 0.f;
    red[tid] = e; __syncthreads();
    for (int o = 128; o; o >>= 1) {
        if (tid < o) red[tid] += red[tid + o];
        __syncthreads();
    }
    const float inv = 1.f / red[0];
    sa[tid] = e * inv;
    if (y == 0 && outAttn && tid < NFEAT)
        outAttn[(size_t)b * TSTEPS * NFEAT + tid] = sa[tid];
    __syncthreads();

    const int j = y * 512 + tid * 2;
    float s0 = 0.f, s1 = 0.f;
    const float* fb = feat + (size_t)b * NFEAT * ENC_Hc + j;
#pragma unroll 8
    for (int n = 0; n < NFEAT; n++) {
        const float al = sa[n];
        const float2 fv = *(const float2*)(fb + (size_t)n * ENC_Hc);
        s0 += al * fv.x; s1 += al * fv.y;
    }
    store_split(XSp, b, XDIM, j, s0, s1);
}

// =============== LSTM pointwise: h, c, XSp tail, HallSp[t][b] ===============
__global__ void lstm_kernel(const float* __restrict__ P,
                            const float* __restrict__ GembT,
                            const float* __restrict__ bhh,
                            float* __restrict__ h,
                            float* __restrict__ c,
                            uint32_t* __restrict__ XSp,
                            uint32_t* __restrict__ HallSp, int t)
{
    const int b = blockIdx.x;
    const int j = blockIdx.y * 256 + threadIdx.x;
    const size_t ps = (size_t)B_ * GDIM;
    float g[4];
#pragma unroll
    for (int q = 0; q < 4; q++) {
        const int col = q * DEC_Hc + j;
        float s = GembT[(size_t)b * GDIM + col] + bhh[col];
#pragma unroll
        for (int z = 0; z < SPLITK_GATES; z++)
            s += P[z * ps + (size_t)b * GDIM + col];
        g[q] = s;
    }
    const float ig = 1.f / (1.f + __expf(-g[0]));
    const float fg = 1.f / (1.f + __expf(-g[1]));
    const float gg = tanhf(g[2]);
    const float og = 1.f / (1.f + __expf(-g[3]));
    const float cn = fg * c[b * DEC_Hc + j] + ig * gg;
    const float hn = og * tanhf(cn);
    c[b * DEC_Hc + j] = cn;
    h[b * DEC_Hc + j] = hn;
    const float hn1 = __shfl_down_sync(0xffffffffu, hn, 1);
    if ((j & 1) == 0) {
        store_split(HallSp, (size_t)t * B_ + b, DEC_Hc, j, hn, hn1);
        store_split(XSp, b, XDIM, ENC_Hc + j, hn, hn1);
    }
}

// ---------------------------------------------------------------------------
extern "C" void kernel_launch(void* const* d_in, const int* in_sizes, int n_in,
                              void* d_out, int out_size)
{
    const float* features = (const float*)d_in[0];
    const int*   captions = (const int*)d_in[1];
    const float* emb_tab  = (const float*)d_in[2];
    const float* W_u  = (const float*)d_in[3];
    const float* b_u  = (const float*)d_in[4];
    const float* W_w  = (const float*)d_in[5];
    const float* b_w  = (const float*)d_in[6];
    const float* W_a  = (const float*)d_in[7];
    const float* W_ih = (const float*)d_in[9];
    const float* b_ih = (const float*)d_in[10];
    const float* W_hh = (const float*)d_in[11];
    const float* b_hh = (const float*)d_in[12];
    const float* W_fc = (const float*)d_in[13];
    const float* b_fc = (const float*)d_in[14];
    const float* W_h0 = (const float*)d_in[15];
    const float* b_h0 = (const float*)d_in[16];
    const float* W_c0 = (const float*)d_in[17];
    const float* b_c0 = (const float*)d_in[18];

    float* outPred = (float*)d_out;
    const size_t predElems = (size_t)B_ * TSTEPS * VOCAB_c;
    const size_t attnElems = (size_t)B_ * TSTEPS * NFEAT;
    float* outAttn =
        ((size_t)out_size >= predElems + attnElems) ? outPred + predElems : nullptr;

    float *pUf, *pFM, *pH, *pC, *pHW, *pSc, *pGP, *pGE;
    uint32_t *pFSp, *pESp, *pXSp, *pHSp, *pWuSp, *pWihSp, *pWfcSp, *pWcatSp;
    cudaGetSymbolAddress((void**)&pUf, g_Uf);
    cudaGetSymbolAddress((void**)&pFM, g_featmean);
    cudaGetSymbolAddress((void**)&pH,  g_h);
    cudaGetSymbolAddress((void**)&pC,  g_c);
    cudaGetSymbolAddress((void**)&pHW, g_hw);
    cudaGetSymbolAddress((void**)&pSc, g_scores);
    cudaGetSymbolAddress((void**)&pGP, g_GatesPart);
    cudaGetSymbolAddress((void**)&pGE, g_Gemb);
    cudaGetSymbolAddress((void**)&pFSp, g_featSp);
    cudaGetSymbolAddress((void**)&pESp, g_EmbSp);
    cudaGetSymbolAddress((void**)&pXSp, g_XSp);
    cudaGetSymbolAddress((void**)&pHSp, g_HallSp);
    cudaGetSymbolAddress((void**)&pWuSp,  g_WuSp);
    cudaGetSymbolAddress((void**)&pWihSp, g_WihSp);
    cudaGetSymbolAddress((void**)&pWfcSp, g_WfcSp);
    cudaGetSymbolAddress((void**)&pWcatSp, g_WcatSp);

    const int SM128 = 3 * (128 * 8 + 128 * 8) * 16;   // 98304
    const int SM64  = 3 * (64 * 8 + 128 * 8) * 16;    // 73728
    cudaFuncSetAttribute(tg<128>, cudaFuncAttributeMaxDynamicSharedMemorySize,
                         SM128);
    cudaFuncSetAttribute(tg<64>, cudaFuncAttributeMaxDynamicSharedMemorySize,
                         SM64);
    const dim3 tsb(32, 8);

    cudaStream_t side;
    cudaStreamCreateWithFlags(&side, cudaStreamNonBlocking);
    cudaEvent_t evStep[TSTEPS];
    for (int i = 0; i < TSTEPS; i++)
        cudaEventCreateWithFlags(&evStep[i], cudaEventDisableTiming);
    cudaEvent_t evFork, evPro, evJoin;
    cudaEventCreateWithFlags(&evFork, cudaEventDisableTiming);
    cudaEventCreateWithFlags(&evPro,  cudaEventDisableTiming);
    cudaEventCreateWithFlags(&evJoin, cudaEventDisableTiming);

    // ---- fork side stream at the very start ----
    cudaEventRecord(evFork, 0);
    cudaStreamWaitEvent(side, evFork, 0);

    // side stream: Wfc split + h0/c0 chain (fast GEMV now)
    ts_split<<<dim3(VOCAB_c / 32, DEC_Hc / 64), tsb, 0, side>>>(
        W_fc, VOCAB_c, pWfcSp, DEC_Hc, 0);
    feat_mean_kernel<<<dim3(B_, ENC_Hc / 256), 256, 0, side>>>(features, pFM);
    hc0_kernel<<<dim3(B_, DEC_Hc / 256), 256, 0, side>>>(
        pFM, W_h0, b_h0, W_c0, b_c0, pH, pC, pXSp);
    cudaEventRecord(evPro, side);

    // main stream prologue
    row_split<<<(int)(((size_t)B_ * NFEAT * ENC_Hc / 4 + 255) / 256), 256>>>(
        features, pFSp, (size_t)B_ * NFEAT * ENC_Hc);
    ts_split<<<dim3(ATTN_c / 32, ENC_Hc / 64), tsb>>>(W_u, ATTN_c, pWuSp,
                                                      ENC_Hc, 0);
    tg<128><<<dim3(B_ * NFEAT / 128, ATTN_c / 128, 1), 256, SM128>>>(
        pFSp, ENC_Hc, pWuSp, ENC_Hc, b_u, pUf, B_ * NFEAT, ATTN_c, ATTN_c,
        ENC_Hc);
    ts_split<<<dim3(GDIM / 32, EMB_c / 64), tsb>>>(W_ih, GDIM, pWihSp,
                                                   EMB_c, 0);
    ts_split<<<dim3(GDIM / 32, ENC_Hc / 64), tsb>>>(W_ih + (size_t)EMB_c * GDIM,
                                                    GDIM, pWcatSp, XDIM, 0);
    ts_split<<<dim3(GDIM / 32, DEC_Hc / 64), tsb>>>(W_hh, GDIM, pWcatSp,
                                                    XDIM, ENC_Hc);
    emb_gather_kernel<<<TSTEPS * B_, 128>>>(captions, emb_tab, pESp);
    tg<128><<<dim3((TSTEPS * B_ + 127) / 128, GDIM / 128, 1), 256, SM128>>>(
        pESp, EMB_c, pWihSp, EMB_c, b_ih, pGE, TSTEPS * B_, GDIM, GDIM,
        EMB_c);

    // main waits for h0/c0/XSp-tail from side before entering the loop
    cudaStreamWaitEvent(0, evPro, 0);

    // ---- recurrence; per-step logits overlapped on side stream ----
    for (int t = 0; t < TSTEPS; t++) {
        hw_kernel<<<dim3(B_, 2), 256>>>(pH, W_w, b_w, pHW);
        scores_kernel<<<dim3(B_, 7), 256>>>(pUf, pHW, W_a, pSc);
        context_kernel<<<dim3(B_, ENC_Hc / 512), 256>>>(
            features, pSc, pXSp,
            outAttn ? outAttn + (size_t)t * NFEAT : nullptr);
        tg<64><<<dim3(1, GDIM / 128, SPLITK_GATES), 256, SM64>>>(
            pXSp, XDIM, pWcatSp, XDIM, nullptr, pGP,
            B_, GDIM, GDIM, XDIM / SPLITK_GATES);
        lstm_kernel<<<dim3(B_, 4), 256>>>(pGP, pGE + (size_t)t * B_ * GDIM,
                                          b_hh, pH, pC, pXSp, pHSp, t);
        cudaEventRecord(evStep[t], 0);
        cudaStreamWaitEvent(side, evStep[t], 0);
        // logits rows for step t: [64,1024] @ WfcSp -> preds[:, t, :]
        tg<64><<<dim3(1, VOCAB_c / 128, 1), 256, SM64, side>>>(
            pHSp + (size_t)t * B_ * DEC_Hc, DEC_Hc, pWfcSp, DEC_Hc, b_fc,
            outPred + (size_t)t * VOCAB_c, B_, VOCAB_c, TSTEPS * VOCAB_c,
            DEC_Hc);
    }

    // join side stream back into the primary stream
    cudaEventRecord(evJoin, side);
    cudaStreamWaitEvent(0, evJoin, 0);
}